// round 12
// baseline (speedup 1.0000x reference)
#include <cuda_runtime.h>
#include <math.h>

// Problem dims (V,E,H,C = 50000,300,512,3; B=64,P=128,Th=64)
#define kB   64
#define kE   300
#define kH   512
#define kH4  2048
#define kPL  128
#define kHL  64
#define kC   3
#define kV   50000

// ---------------- scratch ----------------
__device__ __align__(16) float g_GXp[(size_t)kPL*kB*kH4];   // [t][b][4H]
__device__ __align__(16) float g_GXh[(size_t)kHL*kB*kH4];   // [t][b][4H]
__device__ __align__(16) float g_outp[(size_t)kB*kPL*kH];   // [b][p][h]
__device__ __align__(16) float g_outh[(size_t)kB*kHL*kH];   // [b][t][h]
__device__ __align__(16) float g_a1  [(size_t)kB*kPL*kH];   // [b][p][h]
__device__ __align__(16) float g_qWh [(size_t)kB*kHL*kH];   // [b][t][n]
__device__ __align__(16) float g_hT[2][kH*kB];              // [k][b]
__device__ __align__(16) float g_cT[2][kH*kB];              // [k][b]
__device__ __align__(16) float g_h [2][kB*kH];              // [b][h] (final_rep)
__device__ __align__(16) float g_r  [kB*kH];
__device__ __align__(16) float g_rT [kH*kB];                // [k][b]
__device__ __align__(16) float g_a2 [kB*kH];
__device__ __align__(16) float g_rt [kB*kH];
__device__ __align__(16) float g_rep[kB*kH];

__device__ __forceinline__ float fsigmoid(float x) {
    return __fdividef(1.0f, 1.0f + __expf(-x));
}
__device__ __forceinline__ float ftanh(float x) {
    return 1.0f - __fdividef(2.0f, __expf(2.0f * x) + 1.0f);
}

// ---------------- utility ----------------
__global__ void zero_init() {
    int i = blockIdx.x * blockDim.x + threadIdx.x;
    if (i < kB * kH) {
        g_hT[0][i] = 0.f; g_cT[0][i] = 0.f;
        g_r[i] = 0.f; g_rT[i] = 0.f;
    }
}
__global__ void zero_h0() {
    int i = blockIdx.x * blockDim.x + threadIdx.x;
    if (i < kB * kH) g_hT[0][i] = 0.f;
}
__global__ void zero_out_k(float* out, int n) {
    int i = blockIdx.x * blockDim.x + threadIdx.x;
    if (i < n) out[i] = 0.f;
}

// ---------------- GEMM 64x64 tile, 4x4 microtile, 256 threads (proven) ----
// C[m][n] = bias(n) + sum_k A(m,k) * W[n][k]
// mode 0: emb[premise gather] (K=300) -> g_GXp ; mode 1: emb[hyp] -> g_GXh
// mode 2: g_outp (K=512) -> g_a1 ; mode 3: g_outh (K=512) -> g_qWh
__global__ void __launch_bounds__(256) gemm64(
    int mode, const float* __restrict__ emb, const int* __restrict__ tok,
    const float* __restrict__ W, const float* __restrict__ bias1,
    const float* __restrict__ bias2, int N, int K, int T)
{
    float* Cout = (mode == 0) ? g_GXp : (mode == 1) ? g_GXh
                : (mode == 2) ? g_a1  : g_qWh;

    __shared__ __align__(16) float As[32][68];
    __shared__ __align__(16) float Ws[32][68];

    int tid = threadIdx.x;
    int m0 = blockIdx.y * 64, n0 = blockIdx.x * 64;
    int lr  = tid & 63;
    int lks = (tid >> 6) << 3;

    const float* arow;
    if (mode <= 1) {
        int m = m0 + lr;
        int tt = m >> 6;
        int bb = m & 63;
        int tk = tok[bb * T + tt];
        tk = (tk < 0) ? 0 : ((tk >= kV) ? (kV - 1) : tk);
        arow = emb + (size_t)tk * K;
    } else if (mode == 2) {
        arow = g_outp + (size_t)(m0 + lr) * K;
    } else {
        arow = g_outh + (size_t)(m0 + lr) * K;
    }
    const float* wrow = W + (size_t)(n0 + lr) * K;

    int tx = tid & 15, ty = tid >> 4;
    float acc[4][4] = {};

    for (int k0 = 0; k0 < K; k0 += 32) {
        __syncthreads();
#pragma unroll
        for (int kk2 = 0; kk2 < 8; kk2++) {
            int k = k0 + lks + kk2;
            As[lks + kk2][lr] = (k < K) ? arow[k] : 0.f;
            Ws[lks + kk2][lr] = (k < K) ? wrow[k] : 0.f;
        }
        __syncthreads();
#pragma unroll
        for (int kk = 0; kk < 32; kk++) {
            float4 a = *(const float4*)&As[kk][ty << 2];
            float4 w = *(const float4*)&Ws[kk][tx << 2];
            acc[0][0] += a.x * w.x; acc[0][1] += a.x * w.y;
            acc[0][2] += a.x * w.z; acc[0][3] += a.x * w.w;
            acc[1][0] += a.y * w.x; acc[1][1] += a.y * w.y;
            acc[1][2] += a.y * w.z; acc[1][3] += a.y * w.w;
            acc[2][0] += a.z * w.x; acc[2][1] += a.z * w.y;
            acc[2][2] += a.z * w.z; acc[2][3] += a.z * w.w;
            acc[3][0] += a.w * w.x; acc[3][1] += a.w * w.y;
            acc[3][2] += a.w * w.z; acc[3][3] += a.w * w.w;
        }
    }
#pragma unroll
    for (int i = 0; i < 4; i++) {
        int m = m0 + (ty << 2) + i;
        float* crow = Cout + (size_t)m * N + n0 + (tx << 2);
#pragma unroll
        for (int j = 0; j < 4; j++) {
            float v = acc[i][j];
            int n = n0 + (tx << 2) + j;
            if (bias1) v += bias1[n];
            if (bias2) v += bias2[n];
            crow[j] = v;
        }
    }
}

// ---------------- fused LSTM step v4 ---------------------------------------
// grid 256 x 256. thread: b = tid&63, g = tid>>6 (gate). Block = j-pair j0,j0+1.
// Rows n = g*512 + j0 + {0,1}. h staged in smem [64k][65] (conflict-free:
// bank = (k+b)%32). w: warp-uniform broadcast LDG.128. Gates fused via smem.
__global__ void __launch_bounds__(256) lstm_step4(
    int phase, int t, const float* __restrict__ Whh)
{
    const float* GX = (phase == 0) ? g_GXp + (size_t)t * kB * kH4
                                   : g_GXh + (size_t)t * kB * kH4;
    const float* hT_in = g_hT[t & 1];
    const float* cT_in = g_cT[t & 1];
    float* hT_out = g_hT[(t + 1) & 1];
    float* cT_out = g_cT[(t + 1) & 1];
    float* h_out  = g_h[(t + 1) & 1];

    int tid = threadIdx.x;
    int b = tid & 63;
    int g = tid >> 6;                 // gate 0..3, uniform per warp
    int j0 = blockIdx.x << 1;

    const float* w0 = Whh + ((size_t)g * 512 + j0) * kH;
    const float* w1 = w0 + kH;

    float2 gx = *(const float2*)(GX + (size_t)b * kH4 + g * 512 + j0);
    float a0 = gx.x, a1 = gx.y;

    __shared__ float hs[64][65];      // [k_local][b], pad 65 -> conflict-free

    for (int k0 = 0; k0 < kH; k0 += 64) {
        __syncthreads();
        // stage 64k x 64b chunk, coalesced float4 from hT[k][b]
#pragma unroll
        for (int i = 0; i < 4; i++) {
            int lin = tid + (i << 8);          // 0..1023 float4 units
            int kr = lin >> 4;                 // 0..63
            int c4 = (lin & 15) << 2;          // 0..60
            float4 v = *(const float4*)(hT_in + (size_t)(k0 + kr) * 64 + c4);
            hs[kr][c4 + 0] = v.x; hs[kr][c4 + 1] = v.y;
            hs[kr][c4 + 2] = v.z; hs[kr][c4 + 3] = v.w;
        }
        __syncthreads();
#pragma unroll 4
        for (int kk = 0; kk < 64; kk += 4) {
            float4 u = *(const float4*)(w0 + k0 + kk);
            float4 v = *(const float4*)(w1 + k0 + kk);
            float h0 = hs[kk + 0][b], h1 = hs[kk + 1][b];
            float h2 = hs[kk + 2][b], h3 = hs[kk + 3][b];
            a0 += h0 * u.x + h1 * u.y + h2 * u.z + h3 * u.w;
            a1 += h0 * v.x + h1 * v.y + h2 * v.z + h3 * v.w;
        }
    }

    __shared__ float sg[4][2][64];
    __syncthreads();
    sg[g][0][b] = a0;
    sg[g][1][b] = a1;
    __syncthreads();

    if (g < 2) {
        int j = j0 + g;
        float gi = sg[0][g][b];
        float gf = sg[1][g][b];
        float gg = sg[2][g][b];
        float go = sg[3][g][b];
        float c = fsigmoid(gf) * cT_in[j * 64 + b] + fsigmoid(gi) * ftanh(gg);
        float h = fsigmoid(go) * ftanh(c);
        cT_out[j * 64 + b] = c;
        hT_out[j * 64 + b] = h;
        h_out[b * kH + j]  = h;
        if (phase == 0) g_outp[((size_t)b * kPL + t) * kH + j] = h;
        else            g_outh[((size_t)b * kHL + t) * kH + j] = h;
    }
}

// ---------------- attention precompute v6 (rT staged in smem) --------------
// 1024 rows: row<512 -> a2[b][row] = qWh + r.Wr[row]; else rt = tanh(r.Wt).
// grid 256 x 256. thread: b = tid&63, row = blk*4 + (tid>>6). 1 row/thread.
__global__ void __launch_bounds__(256) att_pre6(
    int t, const float* __restrict__ Wr, const float* __restrict__ Wt)
{
    int tid = threadIdx.x;
    int b = tid & 63;
    int row = (blockIdx.x << 2) + (tid >> 6);
    bool isA = (row < 512);           // uniform per block (4 | 512)

    const float* w0 = isA ? (Wr + (size_t)row * kH)
                          : (Wt + (size_t)(row - 512) * kH);

    float a0 = 0.f;
    __shared__ float rs[64][65];

    for (int k0 = 0; k0 < kH; k0 += 64) {
        __syncthreads();
#pragma unroll
        for (int i = 0; i < 4; i++) {
            int lin = tid + (i << 8);
            int kr = lin >> 4;
            int c4 = (lin & 15) << 2;
            float4 v = *(const float4*)(g_rT + (size_t)(k0 + kr) * 64 + c4);
            rs[kr][c4 + 0] = v.x; rs[kr][c4 + 1] = v.y;
            rs[kr][c4 + 2] = v.z; rs[kr][c4 + 3] = v.w;
        }
        __syncthreads();
#pragma unroll 4
        for (int kk = 0; kk < 64; kk += 4) {
            float4 u = *(const float4*)(w0 + k0 + kk);
            a0 += rs[kk + 0][b] * u.x + rs[kk + 1][b] * u.y
                + rs[kk + 2][b] * u.z + rs[kk + 3][b] * u.w;
        }
    }
    if (isA) g_a2[b * kH + row] = a0 + g_qWh[((size_t)b * kHL + t) * kH + row];
    else     g_rt[b * kH + (row - 512)] = ftanh(a0);
}

// ---------------- attention scores + softmax + r update (one block per b) --
__global__ void __launch_bounds__(512) att_update(const float* __restrict__ w_att)
{
    int b = blockIdx.x;
    int tid = threadIdx.x;
    __shared__ float a2s[512];
    __shared__ float wvs[512];
    __shared__ float ss[128];
    __shared__ float red[16];

    a2s[tid] = g_a2[b * kH + tid];
    wvs[tid] = w_att[tid];
    __syncthreads();

    int p = tid >> 2, sub = tid & 3;
    const float* a1p = g_a1 + ((size_t)b * kPL + p) * kH + (sub << 7);
    const float* a2p = a2s + (sub << 7);
    const float* wvp = wvs + (sub << 7);
    float part = 0.f;
#pragma unroll 4
    for (int k = 0; k < 128; k++)
        part += wvp[k] * ftanh(a1p[k] + a2p[k]);
    part += __shfl_xor_sync(0xffffffffu, part, 1);
    part += __shfl_xor_sync(0xffffffffu, part, 2);
    if (sub == 0) ss[p] = part;
    __syncthreads();

    float v = (tid < 128) ? ss[tid] : -3.4e38f;
#pragma unroll
    for (int o = 16; o; o >>= 1) v = fmaxf(v, __shfl_xor_sync(0xffffffffu, v, o));
    if ((tid & 31) == 0) red[tid >> 5] = v;
    __syncthreads();
    float mx = red[0];
#pragma unroll
    for (int w = 1; w < 16; w++) mx = fmaxf(mx, red[w]);
    __syncthreads();

    float e = 0.f;
    if (tid < 128) e = __expf(ss[tid] - mx);
    float sv = e;
#pragma unroll
    for (int o = 16; o; o >>= 1) sv += __shfl_xor_sync(0xffffffffu, sv, o);
    if ((tid & 31) == 0) red[tid >> 5] = sv;
    __syncthreads();
    float tot = 0.f;
#pragma unroll
    for (int w = 0; w < 16; w++) tot += red[w];
    if (tid < 128) ss[tid] = __fdividef(e, tot);
    __syncthreads();

    float acc = g_rt[b * kH + tid];
    const float* op = g_outp + (size_t)b * kPL * kH + tid;
#pragma unroll 4
    for (int p2 = 0; p2 < kPL; p2++)
        acc += op[(size_t)p2 * kH] * ss[p2];
    g_r[b * kH + tid] = acc;
    g_rT[tid * 64 + b] = acc;
}

// ---------------- final: rep = tanh(r@fc1^T + b1 + hn@fc2^T + b2) ----------
__global__ void __launch_bounds__(128) final_rep(
    const float* __restrict__ w1, const float* __restrict__ b1,
    const float* __restrict__ w2, const float* __restrict__ b2)
{
    __shared__ float rs[64][33];
    __shared__ float hs[64][33];
    int tid = threadIdx.x;
    int b = tid & 63;
    int j = (blockIdx.x << 1) + (tid >> 6);
    const float* hn = g_h[0];

    float acc1 = 0.f, acc2 = 0.f;
    const float* w1p = w1 + (size_t)j * kH;
    const float* w2p = w2 + (size_t)j * kH;

    for (int k0 = 0; k0 < kH; k0 += 32) {
#pragma unroll
        for (int i = 0; i < 4; i++) {
            int l = i * 128 + tid;
            int row = l >> 3;
            int c4 = (l & 7) << 2;
            float4 rv = *(const float4*)(g_r + row * kH + k0 + c4);
            float4 hv = *(const float4*)(hn + row * kH + k0 + c4);
            rs[row][c4 + 0] = rv.x; rs[row][c4 + 1] = rv.y;
            rs[row][c4 + 2] = rv.z; rs[row][c4 + 3] = rv.w;
            hs[row][c4 + 0] = hv.x; hs[row][c4 + 1] = hv.y;
            hs[row][c4 + 2] = hv.z; hs[row][c4 + 3] = hv.w;
        }
        __syncthreads();
#pragma unroll
        for (int k = 0; k < 32; k += 4) {
            float4 w1v = *(const float4*)(w1p + k0 + k);
            float4 w2v = *(const float4*)(w2p + k0 + k);
            acc1 += rs[b][k] * w1v.x + rs[b][k + 1] * w1v.y
                  + rs[b][k + 2] * w1v.z + rs[b][k + 3] * w1v.w;
            acc2 += hs[b][k] * w2v.x + hs[b][k + 1] * w2v.y
                  + hs[b][k + 2] * w2v.z + hs[b][k + 3] * w2v.w;
        }
        __syncthreads();
    }
    g_rep[b * kH + j] = ftanh(acc1 + b1[j] + acc2 + b2[j]);
}

// ---------------- final: out = rep@fc3^T + b3 ----------
__global__ void final_out_k(const float* __restrict__ fc3w,
                            const float* __restrict__ fc3b, float* __restrict__ out)
{
    int b = blockIdx.x, c = blockIdx.y, lane = threadIdx.x;
    float acc = 0.f;
    for (int k = lane; k < kH; k += 32)
        acc += g_rep[b * kH + k] * fc3w[c * kH + k];
#pragma unroll
    for (int o = 16; o; o >>= 1) acc += __shfl_xor_sync(0xffffffffu, acc, o);
    if (lane == 0) out[b * kC + c] = acc + fc3b[c];
}

// ---------------- launch ----------------
extern "C" void kernel_launch(void* const* d_in, const int* in_sizes, int n_in,
                              void* d_out, int out_size)
{
    const void *p_tokP, *p_tokH, *p_emb, *p_fc3w, *p_fc3b;
    const void *wih[2], *whh[2], *bia[4], *sq[6], *v512[3];
    int nwih, nwhh, nbia, nsq, nv;

    auto try_bind = [&](long long mult) -> bool {
        p_tokP = p_tokH = p_emb = p_fc3w = p_fc3b = 0;
        nwih = nwhh = nbia = nsq = nv = 0;
        for (int i = 0; i < 2; i++) { wih[i] = 0; whh[i] = 0; }
        for (int i = 0; i < 4; i++) bia[i] = 0;
        for (int i = 0; i < 6; i++) sq[i] = 0;
        for (int i = 0; i < 3; i++) v512[i] = 0;
        bool over = false;
        for (int i = 0; i < n_in; i++) {
            long long s = (long long)in_sizes[i];
            const void* p = d_in[i];
            if      (s == (long long)kB * kPL * mult)  { if (p_tokP) over = true; p_tokP = p; }
            else if (s == (long long)kB * kHL * mult)  { if (p_tokH) over = true; p_tokH = p; }
            else if (s == (long long)kV * kE * mult)   { if (p_emb)  over = true; p_emb  = p; }
            else if (s == (long long)kH4 * kE * mult)  { if (nwih < 2) wih[nwih++] = p; else over = true; }
            else if (s == (long long)kH4 * kH * mult)  { if (nwhh < 2) whh[nwhh++] = p; else over = true; }
            else if (s == (long long)kH4 * mult)       { if (nbia < 4) bia[nbia++] = p; else over = true; }
            else if (s == (long long)kH * kH * mult)   { if (nsq  < 6) sq [nsq++]  = p; else over = true; }
            else if (s == (long long)kH * mult)        { if (nv   < 3) v512[nv++]  = p; else over = true; }
            else if (s == (long long)kC * kH * mult)   { if (p_fc3w) over = true; p_fc3w = p; }
            else if (s == (long long)kC * mult)        { if (p_fc3b) over = true; p_fc3b = p; }
        }
        return !over && p_tokP && p_tokH && p_emb && p_fc3w && p_fc3b &&
               nwih == 2 && nwhh == 2 && nbia == 4 && nsq == 6 && nv == 3;
    };

    bool ok = try_bind(1);
    if (!ok) ok = try_bind(4);
    if (!ok && n_in >= 22) {
        p_tokP = d_in[0];  p_tokH = d_in[1];  p_emb = d_in[2];
        wih[0] = d_in[3];  whh[0] = d_in[4];  bia[0] = d_in[5];  bia[1] = d_in[6];
        wih[1] = d_in[7];  whh[1] = d_in[8];  bia[2] = d_in[9];  bia[3] = d_in[10];
        sq[0]  = d_in[11]; sq[1]  = d_in[12]; sq[2]  = d_in[13]; sq[3] = d_in[14];
        v512[0]= d_in[15];
        sq[4]  = d_in[16]; v512[1]= d_in[17];
        sq[5]  = d_in[18]; v512[2]= d_in[19];
        p_fc3w = d_in[20]; p_fc3b = d_in[21];
        ok = true;
    }
    if (!ok) {
        int n = out_size / 4;  if (n < 1) n = 1;
        zero_out_k<<<(n + 255) / 256, 256>>>((float*)d_out, n);
        return;
    }

    const int*   premise = (const int*)p_tokP;
    const int*   hyp     = (const int*)p_tokH;
    const float* emb     = (const float*)p_emb;
    const float* Wih1 = (const float*)wih[0]; const float* Whh1 = (const float*)whh[0];
    const float* Wih2 = (const float*)wih[1]; const float* Whh2 = (const float*)whh[1];
    const float* bih1 = (const float*)bia[0]; const float* bhh1 = (const float*)bia[1];
    const float* bih2 = (const float*)bia[2]; const float* bhh2 = (const float*)bia[3];
    const float* W_y  = (const float*)sq[0];  const float* W_h  = (const float*)sq[1];
    const float* W_r  = (const float*)sq[2];  const float* W_t  = (const float*)sq[3];
    const float* fc1_w= (const float*)sq[4];  const float* fc2_w= (const float*)sq[5];
    const float* w_att= (const float*)v512[0];
    const float* fc1_b= (const float*)v512[1];const float* fc2_b= (const float*)v512[2];
    const float* fc3_w= (const float*)p_fc3w; const float* fc3_b= (const float*)p_fc3b;
    float* out = (float*)d_out;

    zero_init<<<128, 256>>>();

    // hoisted input projections (gather fused), K = E = 300
    dim3 gP(kH4 / 64, (kPL * kB) / 64);     // (32, 128)
    gemm64<<<gP, 256>>>(0, emb, premise, Wih1, bih1, bhh1, kH4, kE, kPL);
    dim3 gHyp(kH4 / 64, (kHL * kB) / 64);   // (32, 64)
    gemm64<<<gHyp, 256>>>(1, emb, hyp, Wih2, bih2, bhh2, kH4, kE, kHL);

    // premise LSTM scan
    for (int t = 0; t < kPL; t++)
        lstm_step4<<<256, 256>>>(0, t, Whh1);

    // a1 = out_p @ W_y^T  (K = H = 512)
    dim3 gA1(kH / 64, (kB * kPL) / 64);     // (8, 128)
    gemm64<<<gA1, 256>>>(2, nullptr, nullptr, W_y, nullptr, nullptr, kH, kH, 0);

    // hypothesis LSTM: h0 = 0, c0 = c_p (cT slot 0 after 128 premise steps)
    zero_h0<<<128, 256>>>();
    for (int t = 0; t < kHL; t++)
        lstm_step4<<<256, 256>>>(1, t, Whh2);

    // hoist q@W_h^T for all t: qWh = out_h @ W_h^T
    dim3 gQ(kH / 64, (kB * kHL) / 64);      // (8, 64)
    gemm64<<<gQ, 256>>>(3, nullptr, nullptr, W_h, nullptr, nullptr, kH, kH, 0);

    // word-by-word attention scan
    for (int t = 0; t < kHL; t++) {
        att_pre6<<<256, 256>>>(t, W_r, W_t);
        att_update<<<kB, 512>>>(w_att);
    }

    // classifier head (hn_h in g_h[0] after 64 hyp steps)
    final_rep<<<256, 128>>>(fc1_w, fc1_b, fc2_w, fc2_b);
    dim3 gO(kB, kC);
    final_out_k<<<gO, 32>>>(fc3_w, fc3_b, out);
}

// round 13
// speedup vs baseline: 1.5219x; 1.5219x over previous
#include <cuda_runtime.h>
#include <math.h>

// Problem dims (V,E,H,C = 50000,300,512,3; B=64,P=128,Th=64)
#define kB   64
#define kE   300
#define kH   512
#define kH4  2048
#define kPL  128
#define kHL  64
#define kC   3
#define kV   50000

// ---------------- scratch ----------------
__device__ __align__(16) float g_GXp[(size_t)kPL*kB*kH4];   // [t][b][4H]
__device__ __align__(16) float g_GXh[(size_t)kHL*kB*kH4];   // [t][b][4H]
__device__ __align__(16) float g_outp[(size_t)kB*kPL*kH];   // [b][p][h]
__device__ __align__(16) float g_outh[(size_t)kB*kHL*kH];   // [b][t][h]
__device__ __align__(16) float g_a1  [(size_t)kB*kPL*kH];   // [b][p][h]
__device__ __align__(16) float g_qWh [(size_t)kB*kHL*kH];   // [b][t][n]
__device__ __align__(16) float g_hT[2][kH*kB];              // [k][b]
__device__ __align__(16) float g_cT[2][kH*kB];              // [k][b]
__device__ __align__(16) float g_h [2][kB*kH];              // [b][h] (final_rep)
__device__ __align__(16) float g_r  [kB*kH];
__device__ __align__(16) float g_rT [kH*kB];                // [k][b]
__device__ __align__(16) float g_a2 [kB*kH];
__device__ __align__(16) float g_rt [kB*kH];
__device__ __align__(16) float g_rep[kB*kH];

__device__ __forceinline__ float fsigmoid(float x) {
    return __fdividef(1.0f, 1.0f + __expf(-x));
}
__device__ __forceinline__ float ftanh(float x) {
    return 1.0f - __fdividef(2.0f, __expf(2.0f * x) + 1.0f);
}

// ---------------- utility ----------------
__global__ void zero_init() {
    int i = blockIdx.x * blockDim.x + threadIdx.x;
    if (i < kB * kH) {
        g_hT[0][i] = 0.f; g_cT[0][i] = 0.f;
        g_r[i] = 0.f; g_rT[i] = 0.f;
    }
}
__global__ void zero_h0() {
    int i = blockIdx.x * blockDim.x + threadIdx.x;
    if (i < kB * kH) g_hT[0][i] = 0.f;
}
__global__ void zero_out_k(float* out, int n) {
    int i = blockIdx.x * blockDim.x + threadIdx.x;
    if (i < n) out[i] = 0.f;
}

// ---------------- GEMM 64x64 tile, 4x4 microtile, 256 threads (proven) ----
// C[m][n] = bias(n) + sum_k A(m,k) * W[n][k]
// mode 0: emb[premise gather] (K=300) -> g_GXp ; mode 1: emb[hyp] -> g_GXh
// mode 2: g_outp (K=512) -> g_a1 ; mode 3: g_outh (K=512) -> g_qWh
__global__ void __launch_bounds__(256) gemm64(
    int mode, const float* __restrict__ emb, const int* __restrict__ tok,
    const float* __restrict__ W, const float* __restrict__ bias1,
    const float* __restrict__ bias2, int N, int K, int T)
{
    float* Cout = (mode == 0) ? g_GXp : (mode == 1) ? g_GXh
                : (mode == 2) ? g_a1  : g_qWh;

    __shared__ __align__(16) float As[32][68];
    __shared__ __align__(16) float Ws[32][68];

    int tid = threadIdx.x;
    int m0 = blockIdx.y * 64, n0 = blockIdx.x * 64;
    int lr  = tid & 63;
    int lks = (tid >> 6) << 3;

    const float* arow;
    if (mode <= 1) {
        int m = m0 + lr;
        int tt = m >> 6;
        int bb = m & 63;
        int tk = tok[bb * T + tt];
        tk = (tk < 0) ? 0 : ((tk >= kV) ? (kV - 1) : tk);
        arow = emb + (size_t)tk * K;
    } else if (mode == 2) {
        arow = g_outp + (size_t)(m0 + lr) * K;
    } else {
        arow = g_outh + (size_t)(m0 + lr) * K;
    }
    const float* wrow = W + (size_t)(n0 + lr) * K;

    int tx = tid & 15, ty = tid >> 4;
    float acc[4][4] = {};

    for (int k0 = 0; k0 < K; k0 += 32) {
        __syncthreads();
#pragma unroll
        for (int kk2 = 0; kk2 < 8; kk2++) {
            int k = k0 + lks + kk2;
            As[lks + kk2][lr] = (k < K) ? arow[k] : 0.f;
            Ws[lks + kk2][lr] = (k < K) ? wrow[k] : 0.f;
        }
        __syncthreads();
#pragma unroll
        for (int kk = 0; kk < 32; kk++) {
            float4 a = *(const float4*)&As[kk][ty << 2];
            float4 w = *(const float4*)&Ws[kk][tx << 2];
            acc[0][0] += a.x * w.x; acc[0][1] += a.x * w.y;
            acc[0][2] += a.x * w.z; acc[0][3] += a.x * w.w;
            acc[1][0] += a.y * w.x; acc[1][1] += a.y * w.y;
            acc[1][2] += a.y * w.z; acc[1][3] += a.y * w.w;
            acc[2][0] += a.z * w.x; acc[2][1] += a.z * w.y;
            acc[2][2] += a.z * w.z; acc[2][3] += a.z * w.w;
            acc[3][0] += a.w * w.x; acc[3][1] += a.w * w.y;
            acc[3][2] += a.w * w.z; acc[3][3] += a.w * w.w;
        }
    }
#pragma unroll
    for (int i = 0; i < 4; i++) {
        int m = m0 + (ty << 2) + i;
        float* crow = Cout + (size_t)m * N + n0 + (tx << 2);
#pragma unroll
        for (int j = 0; j < 4; j++) {
            float v = acc[i][j];
            int n = n0 + (tx << 2) + j;
            if (bias1) v += bias1[n];
            if (bias2) v += bias2[n];
            crow[j] = v;
        }
    }
}

// ---------------- fused LSTM step v4 ---------------------------------------
// grid 256 x 256. thread: b = tid&63, g = tid>>6 (gate). Block = j-pair j0,j0+1.
// Rows n = g*512 + j0 + {0,1}. h staged in smem [64k][65] (conflict-free:
// bank = (k+b)%32). w: warp-uniform broadcast LDG.128. Gates fused via smem.
__global__ void __launch_bounds__(256) lstm_step4(
    int phase, int t, const float* __restrict__ Whh)
{
    const float* GX = (phase == 0) ? g_GXp + (size_t)t * kB * kH4
                                   : g_GXh + (size_t)t * kB * kH4;
    const float* hT_in = g_hT[t & 1];
    const float* cT_in = g_cT[t & 1];
    float* hT_out = g_hT[(t + 1) & 1];
    float* cT_out = g_cT[(t + 1) & 1];
    float* h_out  = g_h[(t + 1) & 1];

    int tid = threadIdx.x;
    int b = tid & 63;
    int g = tid >> 6;                 // gate 0..3, uniform per warp
    int j0 = blockIdx.x << 1;

    const float* w0 = Whh + ((size_t)g * 512 + j0) * kH;
    const float* w1 = w0 + kH;

    float2 gx = *(const float2*)(GX + (size_t)b * kH4 + g * 512 + j0);
    float a0 = gx.x, a1 = gx.y;

    __shared__ float hs[64][65];      // [k_local][b], pad 65 -> conflict-free

    for (int k0 = 0; k0 < kH; k0 += 64) {
        __syncthreads();
        // stage 64k x 64b chunk, coalesced float4 from hT[k][b]
#pragma unroll
        for (int i = 0; i < 4; i++) {
            int lin = tid + (i << 8);          // 0..1023 float4 units
            int kr = lin >> 4;                 // 0..63
            int c4 = (lin & 15) << 2;          // 0..60
            float4 v = *(const float4*)(hT_in + (size_t)(k0 + kr) * 64 + c4);
            hs[kr][c4 + 0] = v.x; hs[kr][c4 + 1] = v.y;
            hs[kr][c4 + 2] = v.z; hs[kr][c4 + 3] = v.w;
        }
        __syncthreads();
#pragma unroll 4
        for (int kk = 0; kk < 64; kk += 4) {
            float4 u = *(const float4*)(w0 + k0 + kk);
            float4 v = *(const float4*)(w1 + k0 + kk);
            float h0 = hs[kk + 0][b], h1 = hs[kk + 1][b];
            float h2 = hs[kk + 2][b], h3 = hs[kk + 3][b];
            a0 += h0 * u.x + h1 * u.y + h2 * u.z + h3 * u.w;
            a1 += h0 * v.x + h1 * v.y + h2 * v.z + h3 * v.w;
        }
    }

    __shared__ float sg[4][2][64];
    __syncthreads();
    sg[g][0][b] = a0;
    sg[g][1][b] = a1;
    __syncthreads();

    if (g < 2) {
        int j = j0 + g;
        float gi = sg[0][g][b];
        float gf = sg[1][g][b];
        float gg = sg[2][g][b];
        float go = sg[3][g][b];
        float c = fsigmoid(gf) * cT_in[j * 64 + b] + fsigmoid(gi) * ftanh(gg);
        float h = fsigmoid(go) * ftanh(c);
        cT_out[j * 64 + b] = c;
        hT_out[j * 64 + b] = h;
        h_out[b * kH + j]  = h;
        if (phase == 0) g_outp[((size_t)b * kPL + t) * kH + j] = h;
        else            g_outh[((size_t)b * kHL + t) * kH + j] = h;
    }
}

// ---------------- attention precompute v6 (rT staged in smem) --------------
// 1024 rows: row<512 -> a2[b][row] = qWh + r.Wr[row]; else rt = tanh(r.Wt).
// grid 256 x 256. thread: b = tid&63, row = blk*4 + (tid>>6). 1 row/thread.
__global__ void __launch_bounds__(256) att_pre6(
    int t, const float* __restrict__ Wr, const float* __restrict__ Wt)
{
    int tid = threadIdx.x;
    int b = tid & 63;
    int row = (blockIdx.x << 2) + (tid >> 6);
    bool isA = (row < 512);           // uniform per block (4 | 512)

    const float* w0 = isA ? (Wr + (size_t)row * kH)
                          : (Wt + (size_t)(row - 512) * kH);

    float a0 = 0.f;
    __shared__ float rs[64][65];

    for (int k0 = 0; k0 < kH; k0 += 64) {
        __syncthreads();
#pragma unroll
        for (int i = 0; i < 4; i++) {
            int lin = tid + (i << 8);
            int kr = lin >> 4;
            int c4 = (lin & 15) << 2;
            float4 v = *(const float4*)(g_rT + (size_t)(k0 + kr) * 64 + c4);
            rs[kr][c4 + 0] = v.x; rs[kr][c4 + 1] = v.y;
            rs[kr][c4 + 2] = v.z; rs[kr][c4 + 3] = v.w;
        }
        __syncthreads();
#pragma unroll 4
        for (int kk = 0; kk < 64; kk += 4) {
            float4 u = *(const float4*)(w0 + k0 + kk);
            a0 += rs[kk + 0][b] * u.x + rs[kk + 1][b] * u.y
                + rs[kk + 2][b] * u.z + rs[kk + 3][b] * u.w;
        }
    }
    if (isA) g_a2[b * kH + row] = a0 + g_qWh[((size_t)b * kHL + t) * kH + row];
    else     g_rt[b * kH + (row - 512)] = ftanh(a0);
}

// ---------------- attention scores + softmax + r update (one block per b) --
__global__ void __launch_bounds__(512) att_update(const float* __restrict__ w_att)
{
    int b = blockIdx.x;
    int tid = threadIdx.x;
    __shared__ float a2s[512];
    __shared__ float wvs[512];
    __shared__ float ss[128];
    __shared__ float red[16];

    a2s[tid] = g_a2[b * kH + tid];
    wvs[tid] = w_att[tid];
    __syncthreads();

    int p = tid >> 2, sub = tid & 3;
    const float* a1p = g_a1 + ((size_t)b * kPL + p) * kH + (sub << 7);
    const float* a2p = a2s + (sub << 7);
    const float* wvp = wvs + (sub << 7);
    float part = 0.f;
#pragma unroll 4
    for (int k = 0; k < 128; k++)
        part += wvp[k] * ftanh(a1p[k] + a2p[k]);
    part += __shfl_xor_sync(0xffffffffu, part, 1);
    part += __shfl_xor_sync(0xffffffffu, part, 2);
    if (sub == 0) ss[p] = part;
    __syncthreads();

    float v = (tid < 128) ? ss[tid] : -3.4e38f;
#pragma unroll
    for (int o = 16; o; o >>= 1) v = fmaxf(v, __shfl_xor_sync(0xffffffffu, v, o));
    if ((tid & 31) == 0) red[tid >> 5] = v;
    __syncthreads();
    float mx = red[0];
#pragma unroll
    for (int w = 1; w < 16; w++) mx = fmaxf(mx, red[w]);
    __syncthreads();

    float e = 0.f;
    if (tid < 128) e = __expf(ss[tid] - mx);
    float sv = e;
#pragma unroll
    for (int o = 16; o; o >>= 1) sv += __shfl_xor_sync(0xffffffffu, sv, o);
    if ((tid & 31) == 0) red[tid >> 5] = sv;
    __syncthreads();
    float tot = 0.f;
#pragma unroll
    for (int w = 0; w < 16; w++) tot += red[w];
    if (tid < 128) ss[tid] = __fdividef(e, tot);
    __syncthreads();

    float acc = g_rt[b * kH + tid];
    const float* op = g_outp + (size_t)b * kPL * kH + tid;
#pragma unroll 4
    for (int p2 = 0; p2 < kPL; p2++)
        acc += op[(size_t)p2 * kH] * ss[p2];
    g_r[b * kH + tid] = acc;
    g_rT[tid * 64 + b] = acc;
}

// ---------------- final: rep = tanh(r@fc1^T + b1 + hn@fc2^T + b2) ----------
__global__ void __launch_bounds__(128) final_rep(
    const float* __restrict__ w1, const float* __restrict__ b1,
    const float* __restrict__ w2, const float* __restrict__ b2)
{
    __shared__ float rs[64][33];
    __shared__ float hs[64][33];
    int tid = threadIdx.x;
    int b = tid & 63;
    int j = (blockIdx.x << 1) + (tid >> 6);
    const float* hn = g_h[0];

    float acc1 = 0.f, acc2 = 0.f;
    const float* w1p = w1 + (size_t)j * kH;
    const float* w2p = w2 + (size_t)j * kH;

    for (int k0 = 0; k0 < kH; k0 += 32) {
#pragma unroll
        for (int i = 0; i < 4; i++) {
            int l = i * 128 + tid;
            int row = l >> 3;
            int c4 = (l & 7) << 2;
            float4 rv = *(const float4*)(g_r + row * kH + k0 + c4);
            float4 hv = *(const float4*)(hn + row * kH + k0 + c4);
            rs[row][c4 + 0] = rv.x; rs[row][c4 + 1] = rv.y;
            rs[row][c4 + 2] = rv.z; rs[row][c4 + 3] = rv.w;
            hs[row][c4 + 0] = hv.x; hs[row][c4 + 1] = hv.y;
            hs[row][c4 + 2] = hv.z; hs[row][c4 + 3] = hv.w;
        }
        __syncthreads();
#pragma unroll
        for (int k = 0; k < 32; k += 4) {
            float4 w1v = *(const float4*)(w1p + k0 + k);
            float4 w2v = *(const float4*)(w2p + k0 + k);
            acc1 += rs[b][k] * w1v.x + rs[b][k + 1] * w1v.y
                  + rs[b][k + 2] * w1v.z + rs[b][k + 3] * w1v.w;
            acc2 += hs[b][k] * w2v.x + hs[b][k + 1] * w2v.y
                  + hs[b][k + 2] * w2v.z + hs[b][k + 3] * w2v.w;
        }
        __syncthreads();
    }
    g_rep[b * kH + j] = ftanh(acc1 + b1[j] + acc2 + b2[j]);
}

// ---------------- final: out = rep@fc3^T + b3 ----------
__global__ void final_out_k(const float* __restrict__ fc3w,
                            const float* __restrict__ fc3b, float* __restrict__ out)
{
    int b = blockIdx.x, c = blockIdx.y, lane = threadIdx.x;
    float acc = 0.f;
    for (int k = lane; k < kH; k += 32)
        acc += g_rep[b * kH + k] * fc3w[c * kH + k];
#pragma unroll
    for (int o = 16; o; o >>= 1) acc += __shfl_xor_sync(0xffffffffu, acc, o);
    if (lane == 0) out[b * kC + c] = acc + fc3b[c];
}

// ---------------- launch ----------------
extern "C" void kernel_launch(void* const* d_in, const int* in_sizes, int n_in,
                              void* d_out, int out_size)
{
    const void *p_tokP, *p_tokH, *p_emb, *p_fc3w, *p_fc3b;
    const void *wih[2], *whh[2], *bia[4], *sq[6], *v512[3];
    int nwih, nwhh, nbia, nsq, nv;

    auto try_bind = [&](long long mult) -> bool {
        p_tokP = p_tokH = p_emb = p_fc3w = p_fc3b = 0;
        nwih = nwhh = nbia = nsq = nv = 0;
        for (int i = 0; i < 2; i++) { wih[i] = 0; whh[i] = 0; }
        for (int i = 0; i < 4; i++) bia[i] = 0;
        for (int i = 0; i < 6; i++) sq[i] = 0;
        for (int i = 0; i < 3; i++) v512[i] = 0;
        bool over = false;
        for (int i = 0; i < n_in; i++) {
            long long s = (long long)in_sizes[i];
            const void* p = d_in[i];
            if      (s == (long long)kB * kPL * mult)  { if (p_tokP) over = true; p_tokP = p; }
            else if (s == (long long)kB * kHL * mult)  { if (p_tokH) over = true; p_tokH = p; }
            else if (s == (long long)kV * kE * mult)   { if (p_emb)  over = true; p_emb  = p; }
            else if (s == (long long)kH4 * kE * mult)  { if (nwih < 2) wih[nwih++] = p; else over = true; }
            else if (s == (long long)kH4 * kH * mult)  { if (nwhh < 2) whh[nwhh++] = p; else over = true; }
            else if (s == (long long)kH4 * mult)       { if (nbia < 4) bia[nbia++] = p; else over = true; }
            else if (s == (long long)kH * kH * mult)   { if (nsq  < 6) sq [nsq++]  = p; else over = true; }
            else if (s == (long long)kH * mult)        { if (nv   < 3) v512[nv++]  = p; else over = true; }
            else if (s == (long long)kC * kH * mult)   { if (p_fc3w) over = true; p_fc3w = p; }
            else if (s == (long long)kC * mult)        { if (p_fc3b) over = true; p_fc3b = p; }
        }
        return !over && p_tokP && p_tokH && p_emb && p_fc3w && p_fc3b &&
               nwih == 2 && nwhh == 2 && nbia == 4 && nsq == 6 && nv == 3;
    };

    bool ok = try_bind(1);
    if (!ok) ok = try_bind(4);
    if (!ok && n_in >= 22) {
        p_tokP = d_in[0];  p_tokH = d_in[1];  p_emb = d_in[2];
        wih[0] = d_in[3];  whh[0] = d_in[4];  bia[0] = d_in[5];  bia[1] = d_in[6];
        wih[1] = d_in[7];  whh[1] = d_in[8];  bia[2] = d_in[9];  bia[3] = d_in[10];
        sq[0]  = d_in[11]; sq[1]  = d_in[12]; sq[2]  = d_in[13]; sq[3] = d_in[14];
        v512[0]= d_in[15];
        sq[4]  = d_in[16]; v512[1]= d_in[17];
        sq[5]  = d_in[18]; v512[2]= d_in[19];
        p_fc3w = d_in[20]; p_fc3b = d_in[21];
        ok = true;
    }
    if (!ok) {
        int n = out_size / 4;  if (n < 1) n = 1;
        zero_out_k<<<(n + 255) / 256, 256>>>((float*)d_out, n);
        return;
    }

    const int*   premise = (const int*)p_tokP;
    const int*   hyp     = (const int*)p_tokH;
    const float* emb     = (const float*)p_emb;
    const float* Wih1 = (const float*)wih[0]; const float* Whh1 = (const float*)whh[0];
    const float* Wih2 = (const float*)wih[1]; const float* Whh2 = (const float*)whh[1];
    const float* bih1 = (const float*)bia[0]; const float* bhh1 = (const float*)bia[1];
    const float* bih2 = (const float*)bia[2]; const float* bhh2 = (const float*)bia[3];
    const float* W_y  = (const float*)sq[0];  const float* W_h  = (const float*)sq[1];
    const float* W_r  = (const float*)sq[2];  const float* W_t  = (const float*)sq[3];
    const float* fc1_w= (const float*)sq[4];  const float* fc2_w= (const float*)sq[5];
    const float* w_att= (const float*)v512[0];
    const float* fc1_b= (const float*)v512[1];const float* fc2_b= (const float*)v512[2];
    const float* fc3_w= (const float*)p_fc3w; const float* fc3_b= (const float*)p_fc3b;
    float* out = (float*)d_out;

    zero_init<<<128, 256>>>();

    // hoisted input projections (gather fused), K = E = 300
    dim3 gP(kH4 / 64, (kPL * kB) / 64);     // (32, 128)
    gemm64<<<gP, 256>>>(0, emb, premise, Wih1, bih1, bhh1, kH4, kE, kPL);
    dim3 gHyp(kH4 / 64, (kHL * kB) / 64);   // (32, 64)
    gemm64<<<gHyp, 256>>>(1, emb, hyp, Wih2, bih2, bhh2, kH4, kE, kHL);

    // premise LSTM scan
    for (int t = 0; t < kPL; t++)
        lstm_step4<<<256, 256>>>(0, t, Whh1);

    // a1 = out_p @ W_y^T  (K = H = 512)
    dim3 gA1(kH / 64, (kB * kPL) / 64);     // (8, 128)
    gemm64<<<gA1, 256>>>(2, nullptr, nullptr, W_y, nullptr, nullptr, kH, kH, 0);

    // hypothesis LSTM: h0 = 0, c0 = c_p (cT slot 0 after 128 premise steps)
    zero_h0<<<128, 256>>>();
    for (int t = 0; t < kHL; t++)
        lstm_step4<<<256, 256>>>(1, t, Whh2);

    // hoist q@W_h^T for all t: qWh = out_h @ W_h^T
    dim3 gQ(kH / 64, (kB * kHL) / 64);      // (8, 64)
    gemm64<<<gQ, 256>>>(3, nullptr, nullptr, W_h, nullptr, nullptr, kH, kH, 0);

    // word-by-word attention scan
    for (int t = 0; t < kHL; t++) {
        att_pre6<<<256, 256>>>(t, W_r, W_t);
        att_update<<<kB, 512>>>(w_att);
    }

    // classifier head (hn_h in g_h[0] after 64 hyp steps)
    final_rep<<<256, 128>>>(fc1_w, fc1_b, fc2_w, fc2_b);
    dim3 gO(kB, kC);
    final_out_k<<<gO, 32>>>(fc3_w, fc3_b, out);
}

// round 14
// speedup vs baseline: 1.8956x; 1.2455x over previous
#include <cuda_runtime.h>
#include <math.h>

#define kB   64
#define kE   300
#define kH   512
#define kH4  2048
#define kPL  128
#define kHL  64
#define kC   3
#define kV   50000
#define NBLK 128

// ---------------- scratch ----------------
__device__ __align__(16) float g_GXTp[(size_t)kPL*kH4*kB];  // [t][n][b]
__device__ __align__(16) float g_GXTh[(size_t)kHL*kH4*kB];  // [t][n][b]
__device__ __align__(16) float g_outp[(size_t)kB*kPL*kH];   // [b][p][h]
__device__ __align__(16) float g_outh[(size_t)kB*kHL*kH];   // [b][t][h]
__device__ __align__(16) float g_a1  [(size_t)kB*kPL*kH];   // [b][p][h]
__device__ __align__(16) float g_qWhT[(size_t)kHL*kH*kB];   // [t][n][b]
__device__ __align__(16) float g_hT[2][kH*kB];              // [k][b]
__device__ __align__(16) float g_cT[2][kH*kB];              // [k][b]
__device__ __align__(16) float g_hn [kB*kH];                // final hyp h [b][h]
__device__ __align__(16) float g_r  [kB*kH];
__device__ __align__(16) float g_rT [kH*kB];                // [k][b]
__device__ __align__(16) float g_a2T[kH*kB];                // [n][b]
__device__ __align__(16) float g_rtT[kH*kB];                // [n][b]
__device__ __align__(16) float g_rep[kB*kH];

// ---------------- grid barrier ----------------
__device__ unsigned g_bar_cnt = 0;
__device__ volatile unsigned g_bar_gen = 0;

__device__ __forceinline__ void grid_barrier() {
    __threadfence();
    __syncthreads();
    if (threadIdx.x == 0) {
        unsigned gen = g_bar_gen;
        if (atomicAdd(&g_bar_cnt, 1u) == NBLK - 1) {
            g_bar_cnt = 0;
            __threadfence();
            g_bar_gen = gen + 1;
        } else {
            while (g_bar_gen == gen) __nanosleep(64);
        }
        __threadfence();
    }
    __syncthreads();
}

__device__ __forceinline__ float fsigmoid(float x) {
    return __fdividef(1.0f, 1.0f + __expf(-x));
}
__device__ __forceinline__ float ftanh(float x) {
    return 1.0f - __fdividef(2.0f, __expf(2.0f * x) + 1.0f);
}

__global__ void zero_init() {
    int i = blockIdx.x * blockDim.x + threadIdx.x;
    if (i < kB * kH) { g_hT[0][i] = 0.f; g_cT[0][i] = 0.f; g_rT[i] = 0.f; }
}
__global__ void zero_out_k(float* out, int n) {
    int i = blockIdx.x * blockDim.x + threadIdx.x;
    if (i < n) out[i] = 0.f;
}

// ---------------- GEMM 64x64 tile, 4x4 microtile (proven core) ------------
// mode 0: emb[premise] (K=300) -> g_GXTp[t][n][b]
// mode 1: emb[hyp]     (K=300) -> g_GXTh[t][n][b]
// mode 2: g_outp       (K=512) -> g_a1[m][n]
// mode 3: g_outh       (K=512) -> g_qWhT[t][n][b]  (m = b*kHL + t)
__global__ void __launch_bounds__(256) gemm64(
    int mode, const float* __restrict__ emb, const int* __restrict__ tok,
    const float* __restrict__ W, const float* __restrict__ bias1,
    const float* __restrict__ bias2, int N, int K, int T)
{
    __shared__ __align__(16) float As[32][68];
    __shared__ __align__(16) float Ws[32][68];

    int tid = threadIdx.x;
    int m0 = blockIdx.y * 64, n0 = blockIdx.x * 64;
    int lr  = tid & 63;
    int lks = (tid >> 6) << 3;

    const float* arow;
    if (mode <= 1) {
        int m = m0 + lr;
        int tt = m >> 6, bb = m & 63;
        int tk = tok[bb * T + tt];
        tk = (tk < 0) ? 0 : ((tk >= kV) ? (kV - 1) : tk);
        arow = emb + (size_t)tk * K;
    } else if (mode == 2) {
        arow = g_outp + (size_t)(m0 + lr) * K;
    } else {
        arow = g_outh + (size_t)(m0 + lr) * K;
    }
    const float* wrow = W + (size_t)(n0 + lr) * K;

    int tx = tid & 15, ty = tid >> 4;
    float acc[4][4] = {};

    for (int k0 = 0; k0 < K; k0 += 32) {
        __syncthreads();
#pragma unroll
        for (int kk2 = 0; kk2 < 8; kk2++) {
            int k = k0 + lks + kk2;
            As[lks + kk2][lr] = (k < K) ? arow[k] : 0.f;
            Ws[lks + kk2][lr] = (k < K) ? wrow[k] : 0.f;
        }
        __syncthreads();
#pragma unroll
        for (int kk = 0; kk < 32; kk++) {
            float4 a = *(const float4*)&As[kk][ty << 2];
            float4 w = *(const float4*)&Ws[kk][tx << 2];
            acc[0][0] += a.x*w.x; acc[0][1] += a.x*w.y; acc[0][2] += a.x*w.z; acc[0][3] += a.x*w.w;
            acc[1][0] += a.y*w.x; acc[1][1] += a.y*w.y; acc[1][2] += a.y*w.z; acc[1][3] += a.y*w.w;
            acc[2][0] += a.z*w.x; acc[2][1] += a.z*w.y; acc[2][2] += a.z*w.z; acc[2][3] += a.z*w.w;
            acc[3][0] += a.w*w.x; acc[3][1] += a.w*w.y; acc[3][2] += a.w*w.z; acc[3][3] += a.w*w.w;
        }
    }
#pragma unroll
    for (int i = 0; i < 4; i++) {
        int m = m0 + (ty << 2) + i;
#pragma unroll
        for (int j2 = 0; j2 < 4; j2++) {
            int n = n0 + (tx << 2) + j2;
            float v = acc[i][j2];
            if (bias1) v += bias1[n];
            if (bias2) v += bias2[n];
            if (mode == 0) {
                g_GXTp[((size_t)(m >> 6) * kH4 + n) * 64 + (m & 63)] = v;
            } else if (mode == 1) {
                g_GXTh[((size_t)(m >> 6) * kH4 + n) * 64 + (m & 63)] = v;
            } else if (mode == 2) {
                g_a1[(size_t)m * N + n] = v;
            } else {
                g_qWhT[((size_t)(m & 63) * kH + n) * 64 + (m >> 6)] = v;
            }
        }
    }
}

// ---------------- persistent LSTM: both scans in ONE launch ----------------
// 128 blocks x 256 thr. thread: b = tid&63, jq = tid>>6; j = blk*4 + jq.
// Thread computes ALL 4 gates of j -> in-register gate fusion.
// Block's 16 Whh rows (32KB) cached in smem for the whole scan.
__global__ void __launch_bounds__(256) lstm_persist(
    const float* __restrict__ Whh1, const float* __restrict__ Whh2)
{
    __shared__ __align__(16) float ws[16][512];
    __shared__ float hsT[32][65];

    int tid = threadIdx.x;
    int b  = tid & 63;
    int jq = tid >> 6;
    int j  = (blockIdx.x << 2) + jq;

    for (int phase = 0; phase < 2; phase++) {
        const float* __restrict__ Whh = phase ? Whh2 : Whh1;
        __syncthreads();
        for (int idx = tid; idx < 16 * 128; idx += 256) {
            int row = idx >> 7;               // jql*4 + gl
            int jql = row >> 2, gl = row & 3;
            int c4  = (idx & 127) << 2;
            *(float4*)&ws[row][c4] = *(const float4*)(
                Whh + (size_t)(gl * 512 + (blockIdx.x << 2) + jql) * kH + c4);
        }
        grid_barrier();

        const int T = phase ? kHL : kPL;
        const float* __restrict__ GXT = phase ? g_GXTh : g_GXTp;
        const float* wr0 = ws[jq * 4 + 0];
        const float* wr1 = ws[jq * 4 + 1];
        const float* wr2 = ws[jq * 4 + 2];
        const float* wr3 = ws[jq * 4 + 3];

        for (int t = 0; t < T; t++) {
            const float* __restrict__ hT_in = g_hT[t & 1];

            float ai = GXT[((size_t)t * kH4 +    0 + j) * 64 + b];
            float af = GXT[((size_t)t * kH4 +  512 + j) * 64 + b];
            float ag = GXT[((size_t)t * kH4 + 1024 + j) * 64 + b];
            float ao = GXT[((size_t)t * kH4 + 1536 + j) * 64 + b];

            for (int k0 = 0; k0 < kH; k0 += 32) {
                __syncthreads();
#pragma unroll
                for (int i2 = 0; i2 < 2; i2++) {
                    int lin = tid + (i2 << 8);
                    int kr = lin >> 4, c4 = (lin & 15) << 2;
                    float4 v = __ldcg((const float4*)(hT_in + (size_t)(k0 + kr) * 64 + c4));
                    hsT[kr][c4 + 0] = v.x; hsT[kr][c4 + 1] = v.y;
                    hsT[kr][c4 + 2] = v.z; hsT[kr][c4 + 3] = v.w;
                }
                __syncthreads();
#pragma unroll
                for (int kk = 0; kk < 32; kk += 4) {
                    float h0 = hsT[kk+0][b], h1 = hsT[kk+1][b];
                    float h2 = hsT[kk+2][b], h3 = hsT[kk+3][b];
                    float4 u0 = *(const float4*)(wr0 + k0 + kk);
                    float4 u1 = *(const float4*)(wr1 + k0 + kk);
                    float4 u2 = *(const float4*)(wr2 + k0 + kk);
                    float4 u3 = *(const float4*)(wr3 + k0 + kk);
                    ai += h0*u0.x + h1*u0.y + h2*u0.z + h3*u0.w;
                    af += h0*u1.x + h1*u1.y + h2*u1.z + h3*u1.w;
                    ag += h0*u2.x + h1*u2.y + h2*u2.z + h3*u2.w;
                    ao += h0*u3.x + h1*u3.y + h2*u3.z + h3*u3.w;
                }
            }
            // c read/written by this SAME thread every step -> L1-coherent
            float c = fsigmoid(af) * g_cT[t & 1][j * 64 + b] + fsigmoid(ai) * ftanh(ag);
            float h = fsigmoid(ao) * ftanh(c);
            g_cT[(t + 1) & 1][j * 64 + b] = c;
            g_hT[(t + 1) & 1][j * 64 + b] = h;
            if (phase == 0) {
                g_outp[((size_t)b * kPL + t) * kH + j] = h;
            } else {
                g_outh[((size_t)b * kHL + t) * kH + j] = h;
                if (t == kHL - 1) g_hn[b * kH + j] = h;
            }
            grid_barrier();
        }
        if (phase == 0) {
            // after 128 steps state is in slot 0; hyp: h0 = 0, c0 = c_p kept
            g_hT[0][j * 64 + b] = 0.f;
            grid_barrier();
        }
    }
}

// ---------------- persistent attention scan --------------------------------
// 128 blocks x 256 thr. Blocks 0..63 own 8 Wr rows (a2), 64..127 own 8 Wt rows
// (rt). Phase B: blocks 0..63 each handle batch row b = blk.
__global__ void __launch_bounds__(256) att_persist(
    const float* __restrict__ Wr, const float* __restrict__ Wt,
    const float* __restrict__ w_att)
{
    __shared__ __align__(16) float ws2[8][512];
    __shared__ float rsT[32][65];
    __shared__ float a2s[512];
    __shared__ float wvs[512];
    __shared__ float ss[128];
    __shared__ float red[8];

    int tid = threadIdx.x;
    int b  = tid & 63;
    int lr = tid >> 6;                 // 0..3, 2 rows each
    int blk = blockIdx.x;
    bool isA = (blk < 64);
    int rbase = blk << 3;

    {
        const float* Wsrc = isA ? Wr : Wt;
        int roff = isA ? rbase : (rbase - 512);
        for (int idx = tid; idx < 8 * 128; idx += 256) {
            int row = idx >> 7;
            int c4  = (idx & 127) << 2;
            *(float4*)&ws2[row][c4] = *(const float4*)(Wsrc + (size_t)(roff + row) * kH + c4);
        }
        for (int i = tid; i < 512; i += 256) wvs[i] = w_att[i];
    }
    grid_barrier();

    const float* w0 = ws2[(lr << 1) + 0];
    const float* w1 = ws2[(lr << 1) + 1];
    int r0g = rbase + (lr << 1);

    for (int t = 0; t < kHL; t++) {
        // ---- phase A: 2 weight rows per thread over rT ----
        float a0 = 0.f, a1v = 0.f;
        for (int k0 = 0; k0 < kH; k0 += 32) {
            __syncthreads();
#pragma unroll
            for (int i2 = 0; i2 < 2; i2++) {
                int lin = tid + (i2 << 8);
                int kr = lin >> 4, c4 = (lin & 15) << 2;
                float4 v = __ldcg((const float4*)(g_rT + (size_t)(k0 + kr) * 64 + c4));
                rsT[kr][c4 + 0] = v.x; rsT[kr][c4 + 1] = v.y;
                rsT[kr][c4 + 2] = v.z; rsT[kr][c4 + 3] = v.w;
            }
            __syncthreads();
#pragma unroll
            for (int kk = 0; kk < 32; kk += 4) {
                float r0 = rsT[kk+0][b], r1 = rsT[kk+1][b];
                float r2 = rsT[kk+2][b], r3 = rsT[kk+3][b];
                float4 u = *(const float4*)(w0 + k0 + kk);
                float4 v = *(const float4*)(w1 + k0 + kk);
                a0  += r0*u.x + r1*u.y + r2*u.z + r3*u.w;
                a1v += r0*v.x + r1*v.y + r2*v.z + r3*v.w;
            }
        }
        if (isA) {
            const float* qw = g_qWhT + (size_t)t * kH * 64;
            g_a2T[(size_t)(r0g    ) * 64 + b] = a0  + qw[(size_t)(r0g    ) * 64 + b];
            g_a2T[(size_t)(r0g + 1) * 64 + b] = a1v + qw[(size_t)(r0g + 1) * 64 + b];
        } else {
            g_rtT[(size_t)(r0g - 512) * 64 + b] = ftanh(a0);
            g_rtT[(size_t)(r0g - 511) * 64 + b] = ftanh(a1v);
        }
        grid_barrier();

        // ---- phase B: blocks 0..63, batch row bb = blk ----
        if (isA) {
            int bb = blk;
            for (int i = tid; i < 512; i += 256)
                a2s[i] = __ldcg(g_a2T + (size_t)i * 64 + bb);
            __syncthreads();

            int wid = tid >> 5, lane = tid & 31;
            for (int p = wid; p < kPL; p += 8) {
                const float* a1p = g_a1 + ((size_t)bb * kPL + p) * kH;
                float part = 0.f;
#pragma unroll
                for (int c2 = 0; c2 < 4; c2++) {
                    int kk = c2 * 128 + (lane << 2);
                    float4 av  = *(const float4*)(a1p + kk);
                    float4 a2v = *(const float4*)&a2s[kk];
                    float4 wv4 = *(const float4*)&wvs[kk];
                    part += wv4.x * ftanh(av.x + a2v.x) + wv4.y * ftanh(av.y + a2v.y)
                          + wv4.z * ftanh(av.z + a2v.z) + wv4.w * ftanh(av.w + a2v.w);
                }
#pragma unroll
                for (int o = 16; o; o >>= 1)
                    part += __shfl_xor_sync(0xffffffffu, part, o);
                if (lane == 0) ss[p] = part;
            }
            __syncthreads();

            float v = (tid < 128) ? ss[tid] : -3.4e38f;
#pragma unroll
            for (int o = 16; o; o >>= 1) v = fmaxf(v, __shfl_xor_sync(0xffffffffu, v, o));
            if ((tid & 31) == 0) red[tid >> 5] = v;
            __syncthreads();
            float mx = red[0];
#pragma unroll
            for (int w = 1; w < 8; w++) mx = fmaxf(mx, red[w]);
            __syncthreads();
            float e = 0.f;
            if (tid < 128) e = __expf(ss[tid] - mx);
            float sv = e;
#pragma unroll
            for (int o = 16; o; o >>= 1) sv += __shfl_xor_sync(0xffffffffu, sv, o);
            if ((tid & 31) == 0) red[tid >> 5] = sv;
            __syncthreads();
            float tot = 0.f;
#pragma unroll
            for (int w = 0; w < 8; w++) tot += red[w];
            if (tid < 128) ss[tid] = __fdividef(e, tot);
            __syncthreads();

            for (int hh = tid; hh < kH; hh += 256) {
                float acc = __ldcg(g_rtT + (size_t)hh * 64 + bb);
                const float* op = g_outp + (size_t)bb * kPL * kH + hh;
#pragma unroll 4
                for (int p2 = 0; p2 < kPL; p2++)
                    acc += op[(size_t)p2 * kH] * ss[p2];
                g_rT[(size_t)hh * 64 + bb] = acc;
                if (t == kHL - 1) g_r[bb * kH + hh] = acc;
            }
        }
        grid_barrier();
    }
}

// ---------------- final: rep = tanh(r@fc1^T + b1 + hn@fc2^T + b2) ----------
__global__ void __launch_bounds__(128) final_rep(
    const float* __restrict__ w1, const float* __restrict__ b1,
    const float* __restrict__ w2, const float* __restrict__ b2)
{
    __shared__ float rs[64][33];
    __shared__ float hs[64][33];
    int tid = threadIdx.x;
    int b = tid & 63;
    int j = (blockIdx.x << 1) + (tid >> 6);

    float acc1 = 0.f, acc2 = 0.f;
    const float* w1p = w1 + (size_t)j * kH;
    const float* w2p = w2 + (size_t)j * kH;

    for (int k0 = 0; k0 < kH; k0 += 32) {
#pragma unroll
        for (int i = 0; i < 4; i++) {
            int l = i * 128 + tid;
            int row = l >> 3;
            int c4 = (l & 7) << 2;
            float4 rv = *(const float4*)(g_r + row * kH + k0 + c4);
            float4 hv = *(const float4*)(g_hn + row * kH + k0 + c4);
            rs[row][c4 + 0] = rv.x; rs[row][c4 + 1] = rv.y;
            rs[row][c4 + 2] = rv.z; rs[row][c4 + 3] = rv.w;
            hs[row][c4 + 0] = hv.x; hs[row][c4 + 1] = hv.y;
            hs[row][c4 + 2] = hv.z; hs[row][c4 + 3] = hv.w;
        }
        __syncthreads();
#pragma unroll
        for (int k = 0; k < 32; k += 4) {
            float4 w1v = *(const float4*)(w1p + k0 + k);
            float4 w2v = *(const float4*)(w2p + k0 + k);
            acc1 += rs[b][k]*w1v.x + rs[b][k+1]*w1v.y + rs[b][k+2]*w1v.z + rs[b][k+3]*w1v.w;
            acc2 += hs[b][k]*w2v.x + hs[b][k+1]*w2v.y + hs[b][k+2]*w2v.z + hs[b][k+3]*w2v.w;
        }
        __syncthreads();
    }
    g_rep[b * kH + j] = ftanh(acc1 + b1[j] + acc2 + b2[j]);
}

__global__ void final_out_k(const float* __restrict__ fc3w,
                            const float* __restrict__ fc3b, float* __restrict__ out)
{
    int b = blockIdx.x, c = blockIdx.y, lane = threadIdx.x;
    float acc = 0.f;
    for (int k = lane; k < kH; k += 32)
        acc += g_rep[b * kH + k] * fc3w[c * kH + k];
#pragma unroll
    for (int o = 16; o; o >>= 1) acc += __shfl_xor_sync(0xffffffffu, acc, o);
    if (lane == 0) out[b * kC + c] = acc + fc3b[c];
}

// ---------------- launch ----------------
extern "C" void kernel_launch(void* const* d_in, const int* in_sizes, int n_in,
                              void* d_out, int out_size)
{
    const void *p_tokP, *p_tokH, *p_emb, *p_fc3w, *p_fc3b;
    const void *wih[2], *whh[2], *bia[4], *sq[6], *v512[3];
    int nwih, nwhh, nbia, nsq, nv;

    auto try_bind = [&](long long mult) -> bool {
        p_tokP = p_tokH = p_emb = p_fc3w = p_fc3b = 0;
        nwih = nwhh = nbia = nsq = nv = 0;
        for (int i = 0; i < 2; i++) { wih[i] = 0; whh[i] = 0; }
        for (int i = 0; i < 4; i++) bia[i] = 0;
        for (int i = 0; i < 6; i++) sq[i] = 0;
        for (int i = 0; i < 3; i++) v512[i] = 0;
        bool over = false;
        for (int i = 0; i < n_in; i++) {
            long long s = (long long)in_sizes[i];
            const void* p = d_in[i];
            if      (s == (long long)kB * kPL * mult)  { if (p_tokP) over = true; p_tokP = p; }
            else if (s == (long long)kB * kHL * mult)  { if (p_tokH) over = true; p_tokH = p; }
            else if (s == (long long)kV * kE * mult)   { if (p_emb)  over = true; p_emb  = p; }
            else if (s == (long long)kH4 * kE * mult)  { if (nwih < 2) wih[nwih++] = p; else over = true; }
            else if (s == (long long)kH4 * kH * mult)  { if (nwhh < 2) whh[nwhh++] = p; else over = true; }
            else if (s == (long long)kH4 * mult)       { if (nbia < 4) bia[nbia++] = p; else over = true; }
            else if (s == (long long)kH * kH * mult)   { if (nsq  < 6) sq [nsq++]  = p; else over = true; }
            else if (s == (long long)kH * mult)        { if (nv   < 3) v512[nv++]  = p; else over = true; }
            else if (s == (long long)kC * kH * mult)   { if (p_fc3w) over = true; p_fc3w = p; }
            else if (s == (long long)kC * mult)        { if (p_fc3b) over = true; p_fc3b = p; }
        }
        return !over && p_tokP && p_tokH && p_emb && p_fc3w && p_fc3b &&
               nwih == 2 && nwhh == 2 && nbia == 4 && nsq == 6 && nv == 3;
    };

    bool ok = try_bind(1);
    if (!ok) ok = try_bind(4);
    if (!ok && n_in >= 22) {
        p_tokP = d_in[0];  p_tokH = d_in[1];  p_emb = d_in[2];
        wih[0] = d_in[3];  whh[0] = d_in[4];  bia[0] = d_in[5];  bia[1] = d_in[6];
        wih[1] = d_in[7];  whh[1] = d_in[8];  bia[2] = d_in[9];  bia[3] = d_in[10];
        sq[0]  = d_in[11]; sq[1]  = d_in[12]; sq[2]  = d_in[13]; sq[3] = d_in[14];
        v512[0]= d_in[15];
        sq[4]  = d_in[16]; v512[1]= d_in[17];
        sq[5]  = d_in[18]; v512[2]= d_in[19];
        p_fc3w = d_in[20]; p_fc3b = d_in[21];
        ok = true;
    }
    if (!ok) {
        int n = out_size / 4;  if (n < 1) n = 1;
        zero_out_k<<<(n + 255) / 256, 256>>>((float*)d_out, n);
        return;
    }

    const int*   premise = (const int*)p_tokP;
    const int*   hyp     = (const int*)p_tokH;
    const float* emb     = (const float*)p_emb;
    const float* Wih1 = (const float*)wih[0]; const float* Whh1 = (const float*)whh[0];
    const float* Wih2 = (const float*)wih[1]; const float* Whh2 = (const float*)whh[1];
    const float* bih1 = (const float*)bia[0]; const float* bhh1 = (const float*)bia[1];
    const float* bih2 = (const float*)bia[2]; const float* bhh2 = (const float*)bia[3];
    const float* W_y  = (const float*)sq[0];  const float* W_h  = (const float*)sq[1];
    const float* W_r  = (const float*)sq[2];  const float* W_t  = (const float*)sq[3];
    const float* fc1_w= (const float*)sq[4];  const float* fc2_w= (const float*)sq[5];
    const float* w_att= (const float*)v512[0];
    const float* fc1_b= (const float*)v512[1];const float* fc2_b= (const float*)v512[2];
    const float* fc3_w= (const float*)p_fc3w; const float* fc3_b= (const float*)p_fc3b;
    float* out = (float*)d_out;

    zero_init<<<128, 256>>>();

    dim3 gP(kH4 / 64, (kPL * kB) / 64);
    gemm64<<<gP, 256>>>(0, emb, premise, Wih1, bih1, bhh1, kH4, kE, kPL);
    dim3 gHyp(kH4 / 64, (kHL * kB) / 64);
    gemm64<<<gHyp, 256>>>(1, emb, hyp, Wih2, bih2, bhh2, kH4, kE, kHL);

    // both LSTM scans, one persistent launch
    lstm_persist<<<NBLK, 256>>>(Whh1, Whh2);

    // a1 = out_p @ W_y^T ; qWh = out_h @ W_h^T
    dim3 gA1(kH / 64, (kB * kPL) / 64);
    gemm64<<<gA1, 256>>>(2, nullptr, nullptr, W_y, nullptr, nullptr, kH, kH, 0);
    dim3 gQ(kH / 64, (kB * kHL) / 64);
    gemm64<<<gQ, 256>>>(3, nullptr, nullptr, W_h, nullptr, nullptr, kH, kH, 0);

    // attention scan, one persistent launch
    att_persist<<<NBLK, 256>>>(W_r, W_t, w_att);

    final_rep<<<256, 128>>>(fc1_w, fc1_b, fc2_w, fc2_b);
    dim3 gO(kB, kC);
    final_out_k<<<gO, 32>>>(fc3_w, fc3_b, out);
}

// round 15
// speedup vs baseline: 2.2864x; 1.2062x over previous
#include <cuda_runtime.h>
#include <math.h>

#define kB   64
#define kE   300
#define kH   512
#define kH4  2048
#define kPL  128
#define kHL  64
#define kC   3
#define kV   50000
#define NBLKP 148   // persistent grid: all SMs; blocks >=128 idle at barriers

// ---------------- scratch ----------------
__device__ __align__(16) float g_GXTp[(size_t)kPL*kH4*kB];  // [t][n][b]
__device__ __align__(16) float g_GXTh[(size_t)kHL*kH4*kB];  // [t][n][b]
__device__ __align__(16) float g_outp[(size_t)kB*kPL*kH];   // [b][p][h]
__device__ __align__(16) float g_outh[(size_t)kB*kHL*kH];   // [b][t][h]
__device__ __align__(16) float g_a1  [(size_t)kB*kPL*kH];   // [b][p][h]
__device__ __align__(16) float g_qWhT[(size_t)kHL*kH*kB];   // [t][n][b]
__device__ __align__(16) float g_hT[2][kH*kB];              // [k][b]
__device__ __align__(16) float g_cT[2][kH*kB];              // [k][b]
__device__ __align__(16) float g_hn [kB*kH];
__device__ __align__(16) float g_r  [kB*kH];
__device__ __align__(16) float g_rT [kH*kB];                // [k][b]
__device__ __align__(16) float g_a2T[kH*kB];                // [n][b]
__device__ __align__(16) float g_rtT[kH*kB];                // [n][b]
__device__ __align__(16) float g_rep[kB*kH];

// ---------------- grid barrier ----------------
__device__ unsigned g_bar_cnt = 0;
__device__ volatile unsigned g_bar_gen = 0;

__device__ __forceinline__ void grid_barrier() {
    __threadfence();
    __syncthreads();
    if (threadIdx.x == 0) {
        unsigned gen = g_bar_gen;
        if (atomicAdd(&g_bar_cnt, 1u) == NBLKP - 1) {
            g_bar_cnt = 0;
            __threadfence();
            g_bar_gen = gen + 1;
        } else {
            while (g_bar_gen == gen) __nanosleep(64);
        }
        __threadfence();
    }
    __syncthreads();
}

__device__ __forceinline__ float fsigmoid(float x) {
    return __fdividef(1.0f, 1.0f + __expf(-x));
}
__device__ __forceinline__ float ftanh(float x) {
    return 1.0f - __fdividef(2.0f, __expf(2.0f * x) + 1.0f);
}

__global__ void zero_init() {
    int i = blockIdx.x * blockDim.x + threadIdx.x;
    if (i < kB * kH) { g_hT[0][i] = 0.f; g_cT[0][i] = 0.f; g_rT[i] = 0.f; }
}
__global__ void zero_out_k(float* out, int n) {
    int i = blockIdx.x * blockDim.x + threadIdx.x;
    if (i < n) out[i] = 0.f;
}

// ---------------- GEMM 64x64 tile, 4x4 microtile (proven core) ------------
__global__ void __launch_bounds__(256) gemm64(
    int mode, const float* __restrict__ emb, const int* __restrict__ tok,
    const float* __restrict__ W, const float* __restrict__ bias1,
    const float* __restrict__ bias2, int N, int K, int T)
{
    __shared__ __align__(16) float As[32][68];
    __shared__ __align__(16) float Ws[32][68];

    int tid = threadIdx.x;
    int m0 = blockIdx.y * 64, n0 = blockIdx.x * 64;
    int lr  = tid & 63;
    int lks = (tid >> 6) << 3;

    const float* arow;
    if (mode <= 1) {
        int m = m0 + lr;
        int tt = m >> 6, bb = m & 63;
        int tk = tok[bb * T + tt];
        tk = (tk < 0) ? 0 : ((tk >= kV) ? (kV - 1) : tk);
        arow = emb + (size_t)tk * K;
    } else if (mode == 2) {
        arow = g_outp + (size_t)(m0 + lr) * K;
    } else {
        arow = g_outh + (size_t)(m0 + lr) * K;
    }
    const float* wrow = W + (size_t)(n0 + lr) * K;

    int tx = tid & 15, ty = tid >> 4;
    float acc[4][4] = {};

    for (int k0 = 0; k0 < K; k0 += 32) {
        __syncthreads();
#pragma unroll
        for (int kk2 = 0; kk2 < 8; kk2++) {
            int k = k0 + lks + kk2;
            As[lks + kk2][lr] = (k < K) ? arow[k] : 0.f;
            Ws[lks + kk2][lr] = (k < K) ? wrow[k] : 0.f;
        }
        __syncthreads();
#pragma unroll
        for (int kk = 0; kk < 32; kk++) {
            float4 a = *(const float4*)&As[kk][ty << 2];
            float4 w = *(const float4*)&Ws[kk][tx << 2];
            acc[0][0] += a.x*w.x; acc[0][1] += a.x*w.y; acc[0][2] += a.x*w.z; acc[0][3] += a.x*w.w;
            acc[1][0] += a.y*w.x; acc[1][1] += a.y*w.y; acc[1][2] += a.y*w.z; acc[1][3] += a.y*w.w;
            acc[2][0] += a.z*w.x; acc[2][1] += a.z*w.y; acc[2][2] += a.z*w.z; acc[2][3] += a.z*w.w;
            acc[3][0] += a.w*w.x; acc[3][1] += a.w*w.y; acc[3][2] += a.w*w.z; acc[3][3] += a.w*w.w;
        }
    }
#pragma unroll
    for (int i = 0; i < 4; i++) {
        int m = m0 + (ty << 2) + i;
#pragma unroll
        for (int j2 = 0; j2 < 4; j2++) {
            int n = n0 + (tx << 2) + j2;
            float v = acc[i][j2];
            if (bias1) v += bias1[n];
            if (bias2) v += bias2[n];
            if (mode == 0) {
                g_GXTp[((size_t)(m >> 6) * kH4 + n) * 64 + (m & 63)] = v;
            } else if (mode == 1) {
                g_GXTh[((size_t)(m >> 6) * kH4 + n) * 64 + (m & 63)] = v;
            } else if (mode == 2) {
                g_a1[(size_t)m * N + n] = v;
            } else {
                g_qWhT[((size_t)(m & 63) * kH + n) * 64 + (m >> 6)] = v;
            }
        }
    }
}

// ---------------- persistent LSTM (double-buffered staging) ----------------
// 148 blocks x 256 thr; blocks >=128 idle (barriers only). Active block owns
// j = blk*4 + jq; thread (b, jq) computes all 4 gates of j in registers.
// Whh rows (16, 32KB) in smem for the whole scan. h staged per step in 8
// chunks of 64k with register prefetch overlapping the L2 reads with compute.
__global__ void __launch_bounds__(256) lstm_persist(
    const float* __restrict__ Whh1, const float* __restrict__ Whh2)
{
    __shared__ __align__(16) float ws[16][512];   // 32KB
    __shared__ __align__(16) float hsT[64][64];   // 16KB (stride 64: lanes-by-b conflict-free)

    int tid = threadIdx.x;
    int b  = tid & 63;
    int jq = tid >> 6;
    int blk = blockIdx.x;
    bool active = (blk < 128);
    int j  = (blk << 2) + jq;

    for (int phase = 0; phase < 2; phase++) {
        const float* __restrict__ Whh = phase ? Whh2 : Whh1;
        __syncthreads();
        if (active) {
            for (int idx = tid; idx < 16 * 128; idx += 256) {
                int row = idx >> 7;
                int jql = row >> 2, gl = row & 3;
                int c4  = (idx & 127) << 2;
                *(float4*)&ws[row][c4] = *(const float4*)(
                    Whh + (size_t)(gl * 512 + (blk << 2) + jql) * kH + c4);
            }
        }
        grid_barrier();

        const int T = phase ? kHL : kPL;
        const float* __restrict__ GXT = phase ? g_GXTh : g_GXTp;
        const float* wr0 = ws[jq * 4 + 0];
        const float* wr1 = ws[jq * 4 + 1];
        const float* wr2 = ws[jq * 4 + 2];
        const float* wr3 = ws[jq * 4 + 3];

        for (int t = 0; t < T; t++) {
            if (active) {
                const float* __restrict__ hT_in = g_hT[t & 1];

                float ai = GXT[((size_t)t * kH4 +    0 + j) * 64 + b];
                float af = GXT[((size_t)t * kH4 +  512 + j) * 64 + b];
                float ag = GXT[((size_t)t * kH4 + 1024 + j) * 64 + b];
                float ao = GXT[((size_t)t * kH4 + 1536 + j) * 64 + b];

                // prefetch chunk 0 (64k x 64b = 1024 float4; 4 per thread)
                float4 pre[4];
#pragma unroll
                for (int i2 = 0; i2 < 4; i2++) {
                    int lin = tid + (i2 << 8);
                    pre[i2] = __ldcg((const float4*)(hT_in +
                        (size_t)(lin >> 4) * 64 + ((lin & 15) << 2)));
                }

                for (int cch = 0; cch < 8; cch++) {
                    __syncthreads();
#pragma unroll
                    for (int i2 = 0; i2 < 4; i2++) {
                        int lin = tid + (i2 << 8);
                        *(float4*)&hsT[lin >> 4][(lin & 15) << 2] = pre[i2];
                    }
                    __syncthreads();
                    if (cch < 7) {
#pragma unroll
                        for (int i2 = 0; i2 < 4; i2++) {
                            int lin = tid + (i2 << 8);
                            pre[i2] = __ldcg((const float4*)(hT_in +
                                (size_t)((cch + 1) * 64 + (lin >> 4)) * 64 +
                                ((lin & 15) << 2)));
                        }
                    }
                    int kw = cch << 6;
#pragma unroll 8
                    for (int kk = 0; kk < 64; kk += 4) {
                        float h0 = hsT[kk+0][b], h1 = hsT[kk+1][b];
                        float h2 = hsT[kk+2][b], h3 = hsT[kk+3][b];
                        float4 u0 = *(const float4*)(wr0 + kw + kk);
                        float4 u1 = *(const float4*)(wr1 + kw + kk);
                        float4 u2 = *(const float4*)(wr2 + kw + kk);
                        float4 u3 = *(const float4*)(wr3 + kw + kk);
                        ai += h0*u0.x + h1*u0.y + h2*u0.z + h3*u0.w;
                        af += h0*u1.x + h1*u1.y + h2*u1.z + h3*u1.w;
                        ag += h0*u2.x + h1*u2.y + h2*u2.z + h3*u2.w;
                        ao += h0*u3.x + h1*u3.y + h2*u3.z + h3*u3.w;
                    }
                }
                float c = fsigmoid(af) * g_cT[t & 1][j * 64 + b] + fsigmoid(ai) * ftanh(ag);
                float h = fsigmoid(ao) * ftanh(c);
                g_cT[(t + 1) & 1][j * 64 + b] = c;
                g_hT[(t + 1) & 1][j * 64 + b] = h;
                if (phase == 0) {
                    g_outp[((size_t)b * kPL + t) * kH + j] = h;
                } else {
                    g_outh[((size_t)b * kHL + t) * kH + j] = h;
                    if (t == kHL - 1) g_hn[b * kH + j] = h;
                }
            }
            grid_barrier();
        }
        if (phase == 0) {
            if (active) g_hT[0][j * 64 + b] = 0.f;   // hyp: h0 = 0, keep c_p
            grid_barrier();
        }
    }
}

// ---------------- persistent attention scan --------------------------------
// 148 blocks; blk<64: Wr rows + phase B (batch row blk); 64..127: Wt rows;
// >=128 idle. rT staged with register-prefetch double buffering.
__global__ void __launch_bounds__(256) att_persist(
    const float* __restrict__ Wr, const float* __restrict__ Wt,
    const float* __restrict__ w_att)
{
    __shared__ __align__(16) float ws2[8][512];   // 16KB
    __shared__ __align__(16) float rsT[64][64];   // 16KB
    __shared__ float a2s[512];
    __shared__ float wvs[512];
    __shared__ float ss[128];
    __shared__ float red[8];

    int tid = threadIdx.x;
    int b  = tid & 63;
    int lr = tid >> 6;
    int blk = blockIdx.x;
    bool active = (blk < 128);
    bool isA = (blk < 64);
    int rbase = blk << 3;

    if (active) {
        const float* Wsrc = isA ? Wr : Wt;
        int roff = isA ? rbase : (rbase - 512);
        for (int idx = tid; idx < 8 * 128; idx += 256) {
            int row = idx >> 7;
            int c4  = (idx & 127) << 2;
            *(float4*)&ws2[row][c4] = *(const float4*)(Wsrc + (size_t)(roff + row) * kH + c4);
        }
        if (isA) for (int i = tid; i < 512; i += 256) wvs[i] = w_att[i];
    }
    grid_barrier();

    const float* w0 = ws2[(lr << 1) + 0];
    const float* w1 = ws2[(lr << 1) + 1];
    int r0g = rbase + (lr << 1);

    for (int t = 0; t < kHL; t++) {
        if (active) {
            // ---- phase A: 2 weight rows per thread over rT (double-buffered)
            float a0 = 0.f, a1v = 0.f;
            float4 pre[4];
#pragma unroll
            for (int i2 = 0; i2 < 4; i2++) {
                int lin = tid + (i2 << 8);
                pre[i2] = __ldcg((const float4*)(g_rT +
                    (size_t)(lin >> 4) * 64 + ((lin & 15) << 2)));
            }
            for (int cch = 0; cch < 8; cch++) {
                __syncthreads();
#pragma unroll
                for (int i2 = 0; i2 < 4; i2++) {
                    int lin = tid + (i2 << 8);
                    *(float4*)&rsT[lin >> 4][(lin & 15) << 2] = pre[i2];
                }
                __syncthreads();
                if (cch < 7) {
#pragma unroll
                    for (int i2 = 0; i2 < 4; i2++) {
                        int lin = tid + (i2 << 8);
                        pre[i2] = __ldcg((const float4*)(g_rT +
                            (size_t)((cch + 1) * 64 + (lin >> 4)) * 64 +
                            ((lin & 15) << 2)));
                    }
                }
                int kw = cch << 6;
#pragma unroll 8
                for (int kk = 0; kk < 64; kk += 4) {
                    float r0 = rsT[kk+0][b], r1 = rsT[kk+1][b];
                    float r2 = rsT[kk+2][b], r3 = rsT[kk+3][b];
                    float4 u = *(const float4*)(w0 + kw + kk);
                    float4 v = *(const float4*)(w1 + kw + kk);
                    a0  += r0*u.x + r1*u.y + r2*u.z + r3*u.w;
                    a1v += r0*v.x + r1*v.y + r2*v.z + r3*v.w;
                }
            }
            if (isA) {
                const float* qw = g_qWhT + (size_t)t * kH * 64;
                g_a2T[(size_t)(r0g    ) * 64 + b] = a0  + qw[(size_t)(r0g    ) * 64 + b];
                g_a2T[(size_t)(r0g + 1) * 64 + b] = a1v + qw[(size_t)(r0g + 1) * 64 + b];
            } else {
                g_rtT[(size_t)(r0g - 512) * 64 + b] = ftanh(a0);
                g_rtT[(size_t)(r0g - 511) * 64 + b] = ftanh(a1v);
            }
        }
        grid_barrier();

        // ---- phase B: blocks 0..63, batch row bb = blk ----
        if (isA) {
            int bb = blk;
            for (int i = tid; i < 512; i += 256)
                a2s[i] = __ldcg(g_a2T + (size_t)i * 64 + bb);
            __syncthreads();

            int wid = tid >> 5, lane = tid & 31;
            for (int p = wid; p < kPL; p += 8) {
                const float* a1p = g_a1 + ((size_t)bb * kPL + p) * kH;
                float part = 0.f;
#pragma unroll
                for (int c2 = 0; c2 < 4; c2++) {
                    int kk = c2 * 128 + (lane << 2);
                    float4 av  = *(const float4*)(a1p + kk);
                    float4 a2v = *(const float4*)&a2s[kk];
                    float4 wv4 = *(const float4*)&wvs[kk];
                    part += wv4.x * ftanh(av.x + a2v.x) + wv4.y * ftanh(av.y + a2v.y)
                          + wv4.z * ftanh(av.z + a2v.z) + wv4.w * ftanh(av.w + a2v.w);
                }
#pragma unroll
                for (int o = 16; o; o >>= 1)
                    part += __shfl_xor_sync(0xffffffffu, part, o);
                if (lane == 0) ss[p] = part;
            }
            __syncthreads();

            float v = (tid < 128) ? ss[tid] : -3.4e38f;
#pragma unroll
            for (int o = 16; o; o >>= 1) v = fmaxf(v, __shfl_xor_sync(0xffffffffu, v, o));
            if ((tid & 31) == 0) red[tid >> 5] = v;
            __syncthreads();
            float mx = red[0];
#pragma unroll
            for (int w = 1; w < 8; w++) mx = fmaxf(mx, red[w]);
            __syncthreads();
            float e = 0.f;
            if (tid < 128) e = __expf(ss[tid] - mx);
            float sv = e;
#pragma unroll
            for (int o = 16; o; o >>= 1) sv += __shfl_xor_sync(0xffffffffu, sv, o);
            if ((tid & 31) == 0) red[tid >> 5] = sv;
            __syncthreads();
            float tot = 0.f;
#pragma unroll
            for (int w = 0; w < 8; w++) tot += red[w];
            if (tid < 128) ss[tid] = __fdividef(e, tot);
            __syncthreads();

            for (int hh = tid; hh < kH; hh += 256) {
                float acc = __ldcg(g_rtT + (size_t)hh * 64 + bb);
                const float* op = g_outp + (size_t)bb * kPL * kH + hh;
#pragma unroll 8
                for (int p2 = 0; p2 < kPL; p2++)
                    acc += op[(size_t)p2 * kH] * ss[p2];
                g_rT[(size_t)hh * 64 + bb] = acc;
                if (t == kHL - 1) g_r[bb * kH + hh] = acc;
            }
        }
        grid_barrier();
    }
}

// ---------------- final head ----------------
__global__ void __launch_bounds__(128) final_rep(
    const float* __restrict__ w1, const float* __restrict__ b1,
    const float* __restrict__ w2, const float* __restrict__ b2)
{
    __shared__ float rs[64][33];
    __shared__ float hs[64][33];
    int tid = threadIdx.x;
    int b = tid & 63;
    int j = (blockIdx.x << 1) + (tid >> 6);

    float acc1 = 0.f, acc2 = 0.f;
    const float* w1p = w1 + (size_t)j * kH;
    const float* w2p = w2 + (size_t)j * kH;

    for (int k0 = 0; k0 < kH; k0 += 32) {
#pragma unroll
        for (int i = 0; i < 4; i++) {
            int l = i * 128 + tid;
            int row = l >> 3;
            int c4 = (l & 7) << 2;
            float4 rv = *(const float4*)(g_r + row * kH + k0 + c4);
            float4 hv = *(const float4*)(g_hn + row * kH + k0 + c4);
            rs[row][c4 + 0] = rv.x; rs[row][c4 + 1] = rv.y;
            rs[row][c4 + 2] = rv.z; rs[row][c4 + 3] = rv.w;
            hs[row][c4 + 0] = hv.x; hs[row][c4 + 1] = hv.y;
            hs[row][c4 + 2] = hv.z; hs[row][c4 + 3] = hv.w;
        }
        __syncthreads();
#pragma unroll
        for (int k = 0; k < 32; k += 4) {
            float4 w1v = *(const float4*)(w1p + k0 + k);
            float4 w2v = *(const float4*)(w2p + k0 + k);
            acc1 += rs[b][k]*w1v.x + rs[b][k+1]*w1v.y + rs[b][k+2]*w1v.z + rs[b][k+3]*w1v.w;
            acc2 += hs[b][k]*w2v.x + hs[b][k+1]*w2v.y + hs[b][k+2]*w2v.z + hs[b][k+3]*w2v.w;
        }
        __syncthreads();
    }
    g_rep[b * kH + j] = ftanh(acc1 + b1[j] + acc2 + b2[j]);
}

__global__ void final_out_k(const float* __restrict__ fc3w,
                            const float* __restrict__ fc3b, float* __restrict__ out)
{
    int b = blockIdx.x, c = blockIdx.y, lane = threadIdx.x;
    float acc = 0.f;
    for (int k = lane; k < kH; k += 32)
        acc += g_rep[b * kH + k] * fc3w[c * kH + k];
#pragma unroll
    for (int o = 16; o; o >>= 1) acc += __shfl_xor_sync(0xffffffffu, acc, o);
    if (lane == 0) out[b * kC + c] = acc + fc3b[c];
}

// ---------------- launch ----------------
extern "C" void kernel_launch(void* const* d_in, const int* in_sizes, int n_in,
                              void* d_out, int out_size)
{
    const void *p_tokP, *p_tokH, *p_emb, *p_fc3w, *p_fc3b;
    const void *wih[2], *whh[2], *bia[4], *sq[6], *v512[3];
    int nwih, nwhh, nbia, nsq, nv;

    auto try_bind = [&](long long mult) -> bool {
        p_tokP = p_tokH = p_emb = p_fc3w = p_fc3b = 0;
        nwih = nwhh = nbia = nsq = nv = 0;
        for (int i = 0; i < 2; i++) { wih[i] = 0; whh[i] = 0; }
        for (int i = 0; i < 4; i++) bia[i] = 0;
        for (int i = 0; i < 6; i++) sq[i] = 0;
        for (int i = 0; i < 3; i++) v512[i] = 0;
        bool over = false;
        for (int i = 0; i < n_in; i++) {
            long long s = (long long)in_sizes[i];
            const void* p = d_in[i];
            if      (s == (long long)kB * kPL * mult)  { if (p_tokP) over = true; p_tokP = p; }
            else if (s == (long long)kB * kHL * mult)  { if (p_tokH) over = true; p_tokH = p; }
            else if (s == (long long)kV * kE * mult)   { if (p_emb)  over = true; p_emb  = p; }
            else if (s == (long long)kH4 * kE * mult)  { if (nwih < 2) wih[nwih++] = p; else over = true; }
            else if (s == (long long)kH4 * kH * mult)  { if (nwhh < 2) whh[nwhh++] = p; else over = true; }
            else if (s == (long long)kH4 * mult)       { if (nbia < 4) bia[nbia++] = p; else over = true; }
            else if (s == (long long)kH * kH * mult)   { if (nsq  < 6) sq [nsq++]  = p; else over = true; }
            else if (s == (long long)kH * mult)        { if (nv   < 3) v512[nv++]  = p; else over = true; }
            else if (s == (long long)kC * kH * mult)   { if (p_fc3w) over = true; p_fc3w = p; }
            else if (s == (long long)kC * mult)        { if (p_fc3b) over = true; p_fc3b = p; }
        }
        return !over && p_tokP && p_tokH && p_emb && p_fc3w && p_fc3b &&
               nwih == 2 && nwhh == 2 && nbia == 4 && nsq == 6 && nv == 3;
    };

    bool ok = try_bind(1);
    if (!ok) ok = try_bind(4);
    if (!ok && n_in >= 22) {
        p_tokP = d_in[0];  p_tokH = d_in[1];  p_emb = d_in[2];
        wih[0] = d_in[3];  whh[0] = d_in[4];  bia[0] = d_in[5];  bia[1] = d_in[6];
        wih[1] = d_in[7];  whh[1] = d_in[8];  bia[2] = d_in[9];  bia[3] = d_in[10];
        sq[0]  = d_in[11]; sq[1]  = d_in[12]; sq[2]  = d_in[13]; sq[3] = d_in[14];
        v512[0]= d_in[15];
        sq[4]  = d_in[16]; v512[1]= d_in[17];
        sq[5]  = d_in[18]; v512[2]= d_in[19];
        p_fc3w = d_in[20]; p_fc3b = d_in[21];
        ok = true;
    }
    if (!ok) {
        int n = out_size / 4;  if (n < 1) n = 1;
        zero_out_k<<<(n + 255) / 256, 256>>>((float*)d_out, n);
        return;
    }

    const int*   premise = (const int*)p_tokP;
    const int*   hyp     = (const int*)p_tokH;
    const float* emb     = (const float*)p_emb;
    const float* Wih1 = (const float*)wih[0]; const float* Whh1 = (const float*)whh[0];
    const float* Wih2 = (const float*)wih[1]; const float* Whh2 = (const float*)whh[1];
    const float* bih1 = (const float*)bia[0]; const float* bhh1 = (const float*)bia[1];
    const float* bih2 = (const float*)bia[2]; const float* bhh2 = (const float*)bia[3];
    const float* W_y  = (const float*)sq[0];  const float* W_h  = (const float*)sq[1];
    const float* W_r  = (const float*)sq[2];  const float* W_t  = (const float*)sq[3];
    const float* fc1_w= (const float*)sq[4];  const float* fc2_w= (const float*)sq[5];
    const float* w_att= (const float*)v512[0];
    const float* fc1_b= (const float*)v512[1];const float* fc2_b= (const float*)v512[2];
    const float* fc3_w= (const float*)p_fc3w; const float* fc3_b= (const float*)p_fc3b;
    float* out = (float*)d_out;

    zero_init<<<128, 256>>>();

    dim3 gP(kH4 / 64, (kPL * kB) / 64);
    gemm64<<<gP, 256>>>(0, emb, premise, Wih1, bih1, bhh1, kH4, kE, kPL);
    dim3 gHyp(kH4 / 64, (kHL * kB) / 64);
    gemm64<<<gHyp, 256>>>(1, emb, hyp, Wih2, bih2, bhh2, kH4, kE, kHL);

    lstm_persist<<<NBLKP, 256>>>(Whh1, Whh2);

    dim3 gA1(kH / 64, (kB * kPL) / 64);
    gemm64<<<gA1, 256>>>(2, nullptr, nullptr, W_y, nullptr, nullptr, kH, kH, 0);
    dim3 gQ(kH / 64, (kB * kHL) / 64);
    gemm64<<<gQ, 256>>>(3, nullptr, nullptr, W_h, nullptr, nullptr, kH, kH, 0);

    att_persist<<<NBLKP, 256>>>(W_r, W_t, w_att);

    final_rep<<<256, 128>>>(fc1_w, fc1_b, fc2_w, fc2_b);
    dim3 gO(kB, kC);
    final_out_k<<<gO, 32>>>(fc3_w, fc3_b, out);
}

// round 16
// speedup vs baseline: 2.5135x; 1.0993x over previous
#include <cuda_runtime.h>
#include <math.h>

#define kB   64
#define kE   300
#define kH   512
#define kH4  2048
#define kPL  128
#define kHL  64
#define kC   3
#define kV   50000
#define NBLKP 148

// ---------------- scratch ----------------
__device__ __align__(16) float g_GXTp[(size_t)kPL*kH4*kB];  // [t][n][b]
__device__ __align__(16) float g_GXTh[(size_t)kHL*kH4*kB];  // [t][n][b]
__device__ __align__(16) float g_outp[(size_t)kB*kPL*kH];   // [b][p][h]
__device__ __align__(16) float g_outh[(size_t)kB*kHL*kH];   // [b][t][h]
__device__ __align__(16) float g_a1  [(size_t)kB*kPL*kH];   // [b][p][h]
__device__ __align__(16) float g_qWhT[(size_t)kHL*kH*kB];   // [t][n][b]
__device__ __align__(16) float g_hT[2][kH*kB];              // [k][b]
__device__ __align__(16) float g_cT[2][kH*kB];              // [k][b]
__device__ __align__(16) float g_hn [kB*kH];
__device__ __align__(16) float g_r  [kB*kH];
__device__ __align__(16) float g_rT [kH*kB];                // [k][b]
__device__ __align__(16) float g_a2T[kH*kB];                // [n][b]
__device__ __align__(16) float g_rtT[kH*kB];                // [n][b]
__device__ __align__(16) float g_ss [kB*kPL];               // [b][p] scores scratch
__device__ __align__(16) float g_rep[kB*kH];

// ---------------- bucketed grid barrier (8 parallel counters) --------------
__device__ unsigned g_cnt8[8];
__device__ unsigned g_master = 0;
__device__ volatile unsigned g_gen = 0;

__device__ __forceinline__ void grid_barrier() {
    __threadfence();
    __syncthreads();
    if (threadIdx.x == 0) {
        unsigned gen = g_gen;
        int bkt = blockIdx.x & 7;
        unsigned sz = (bkt < 4) ? 19u : 18u;   // 148 = 4*19 + 4*18
        if (atomicAdd(&g_cnt8[bkt], 1u) == sz - 1) {
            g_cnt8[bkt] = 0;
            if (atomicAdd(&g_master, 1u) == 7u) {
                g_master = 0;
                __threadfence();
                g_gen = gen + 1;
            }
        }
        while (g_gen == gen) __nanosleep(32);
        __threadfence();
    }
    __syncthreads();
}

__device__ __forceinline__ float fsigmoid(float x) {
    return __fdividef(1.0f, 1.0f + __expf(-x));
}
__device__ __forceinline__ float ftanh(float x) {
    return 1.0f - __fdividef(2.0f, __expf(2.0f * x) + 1.0f);
}
// HW tanh (1 MUFU) — used ONLY for attention scores (error absorbed by softmax)
__device__ __forceinline__ float htanh(float x) {
    float y;
    asm("tanh.approx.f32 %0, %1;" : "=f"(y) : "f"(x));
    return y;
}

__global__ void zero_init() {
    int i = blockIdx.x * blockDim.x + threadIdx.x;
    if (i < kB * kH) { g_hT[0][i] = 0.f; g_cT[0][i] = 0.f; g_rT[i] = 0.f; }
}
__global__ void zero_out_k(float* out, int n) {
    int i = blockIdx.x * blockDim.x + threadIdx.x;
    if (i < n) out[i] = 0.f;
}

// ---------------- GEMM 64x64 tile, 4x4 microtile (proven core) ------------
__global__ void __launch_bounds__(256) gemm64(
    int mode, const float* __restrict__ emb, const int* __restrict__ tok,
    const float* __restrict__ W, const float* __restrict__ bias1,
    const float* __restrict__ bias2, int N, int K, int T)
{
    __shared__ __align__(16) float As[32][68];
    __shared__ __align__(16) float Ws[32][68];

    int tid = threadIdx.x;
    int m0 = blockIdx.y * 64, n0 = blockIdx.x * 64;
    int lr  = tid & 63;
    int lks = (tid >> 6) << 3;

    const float* arow;
    if (mode <= 1) {
        int m = m0 + lr;
        int tt = m >> 6, bb = m & 63;
        int tk = tok[bb * T + tt];
        tk = (tk < 0) ? 0 : ((tk >= kV) ? (kV - 1) : tk);
        arow = emb + (size_t)tk * K;
    } else if (mode == 2) {
        arow = g_outp + (size_t)(m0 + lr) * K;
    } else {
        arow = g_outh + (size_t)(m0 + lr) * K;
    }
    const float* wrow = W + (size_t)(n0 + lr) * K;

    int tx = tid & 15, ty = tid >> 4;
    float acc[4][4] = {};

    for (int k0 = 0; k0 < K; k0 += 32) {
        __syncthreads();
#pragma unroll
        for (int kk2 = 0; kk2 < 8; kk2++) {
            int k = k0 + lks + kk2;
            As[lks + kk2][lr] = (k < K) ? arow[k] : 0.f;
            Ws[lks + kk2][lr] = (k < K) ? wrow[k] : 0.f;
        }
        __syncthreads();
#pragma unroll
        for (int kk = 0; kk < 32; kk++) {
            float4 a = *(const float4*)&As[kk][ty << 2];
            float4 w = *(const float4*)&Ws[kk][tx << 2];
            acc[0][0] += a.x*w.x; acc[0][1] += a.x*w.y; acc[0][2] += a.x*w.z; acc[0][3] += a.x*w.w;
            acc[1][0] += a.y*w.x; acc[1][1] += a.y*w.y; acc[1][2] += a.y*w.z; acc[1][3] += a.y*w.w;
            acc[2][0] += a.z*w.x; acc[2][1] += a.z*w.y; acc[2][2] += a.z*w.z; acc[2][3] += a.z*w.w;
            acc[3][0] += a.w*w.x; acc[3][1] += a.w*w.y; acc[3][2] += a.w*w.z; acc[3][3] += a.w*w.w;
        }
    }
#pragma unroll
    for (int i = 0; i < 4; i++) {
        int m = m0 + (ty << 2) + i;
#pragma unroll
        for (int j2 = 0; j2 < 4; j2++) {
            int n = n0 + (tx << 2) + j2;
            float v = acc[i][j2];
            if (bias1) v += bias1[n];
            if (bias2) v += bias2[n];
            if (mode == 0) {
                g_GXTp[((size_t)(m >> 6) * kH4 + n) * 64 + (m & 63)] = v;
            } else if (mode == 1) {
                g_GXTh[((size_t)(m >> 6) * kH4 + n) * 64 + (m & 63)] = v;
            } else if (mode == 2) {
                g_a1[(size_t)m * N + n] = v;
            } else {
                g_qWhT[((size_t)(m & 63) * kH + n) * 64 + (m >> 6)] = v;
            }
        }
    }
}

// ---------------- persistent LSTM (proven R15 structure) -------------------
__global__ void __launch_bounds__(256) lstm_persist(
    const float* __restrict__ Whh1, const float* __restrict__ Whh2)
{
    __shared__ __align__(16) float ws[16][512];
    __shared__ __align__(16) float hsT[64][64];

    int tid = threadIdx.x;
    int b  = tid & 63;
    int jq = tid >> 6;
    int blk = blockIdx.x;
    bool active = (blk < 128);
    int j  = (blk << 2) + jq;

    for (int phase = 0; phase < 2; phase++) {
        const float* __restrict__ Whh = phase ? Whh2 : Whh1;
        __syncthreads();
        if (active) {
            for (int idx = tid; idx < 16 * 128; idx += 256) {
                int row = idx >> 7;
                int jql = row >> 2, gl = row & 3;
                int c4  = (idx & 127) << 2;
                *(float4*)&ws[row][c4] = *(const float4*)(
                    Whh + (size_t)(gl * 512 + (blk << 2) + jql) * kH + c4);
            }
        }
        grid_barrier();

        const int T = phase ? kHL : kPL;
        const float* __restrict__ GXT = phase ? g_GXTh : g_GXTp;
        const float* wr0 = ws[jq * 4 + 0];
        const float* wr1 = ws[jq * 4 + 1];
        const float* wr2 = ws[jq * 4 + 2];
        const float* wr3 = ws[jq * 4 + 3];

        for (int t = 0; t < T; t++) {
            if (active) {
                const float* __restrict__ hT_in = g_hT[t & 1];

                float ai = GXT[((size_t)t * kH4 +    0 + j) * 64 + b];
                float af = GXT[((size_t)t * kH4 +  512 + j) * 64 + b];
                float ag = GXT[((size_t)t * kH4 + 1024 + j) * 64 + b];
                float ao = GXT[((size_t)t * kH4 + 1536 + j) * 64 + b];

                float4 pre[4];
#pragma unroll
                for (int i2 = 0; i2 < 4; i2++) {
                    int lin = tid + (i2 << 8);
                    pre[i2] = __ldcg((const float4*)(hT_in +
                        (size_t)(lin >> 4) * 64 + ((lin & 15) << 2)));
                }

                for (int cch = 0; cch < 8; cch++) {
                    __syncthreads();
#pragma unroll
                    for (int i2 = 0; i2 < 4; i2++) {
                        int lin = tid + (i2 << 8);
                        *(float4*)&hsT[lin >> 4][(lin & 15) << 2] = pre[i2];
                    }
                    __syncthreads();
                    if (cch < 7) {
#pragma unroll
                        for (int i2 = 0; i2 < 4; i2++) {
                            int lin = tid + (i2 << 8);
                            pre[i2] = __ldcg((const float4*)(hT_in +
                                (size_t)((cch + 1) * 64 + (lin >> 4)) * 64 +
                                ((lin & 15) << 2)));
                        }
                    }
                    int kw = cch << 6;
#pragma unroll 8
                    for (int kk = 0; kk < 64; kk += 4) {
                        float h0 = hsT[kk+0][b], h1 = hsT[kk+1][b];
                        float h2 = hsT[kk+2][b], h3 = hsT[kk+3][b];
                        float4 u0 = *(const float4*)(wr0 + kw + kk);
                        float4 u1 = *(const float4*)(wr1 + kw + kk);
                        float4 u2 = *(const float4*)(wr2 + kw + kk);
                        float4 u3 = *(const float4*)(wr3 + kw + kk);
                        ai += h0*u0.x + h1*u0.y + h2*u0.z + h3*u0.w;
                        af += h0*u1.x + h1*u1.y + h2*u1.z + h3*u1.w;
                        ag += h0*u2.x + h1*u2.y + h2*u2.z + h3*u2.w;
                        ao += h0*u3.x + h1*u3.y + h2*u3.z + h3*u3.w;
                    }
                }
                float c = fsigmoid(af) * g_cT[t & 1][j * 64 + b] + fsigmoid(ai) * ftanh(ag);
                float h = fsigmoid(ao) * ftanh(c);
                g_cT[(t + 1) & 1][j * 64 + b] = c;
                g_hT[(t + 1) & 1][j * 64 + b] = h;
                if (phase == 0) {
                    g_outp[((size_t)b * kPL + t) * kH + j] = h;
                } else {
                    g_outh[((size_t)b * kHL + t) * kH + j] = h;
                    if (t == kHL - 1) g_hn[b * kH + j] = h;
                }
            }
            grid_barrier();
        }
        if (phase == 0) {
            if (active) g_hT[0][j * 64 + b] = 0.f;
            grid_barrier();
        }
    }
}

// ---------------- persistent attention scan --------------------------------
// Per t: A (a2/rt GEMVs, blocks<128) | B1 (scores, blocks<128, half-p each,
// tanh.approx) | B2 (softmax + r update, blocks<64).
__global__ void __launch_bounds__(256) att_persist(
    const float* __restrict__ Wr, const float* __restrict__ Wt,
    const float* __restrict__ w_att)
{
    __shared__ __align__(16) float ws2[8][512];
    __shared__ __align__(16) float rsT[64][64];
    __shared__ float a2s[512];
    __shared__ float wvs[512];
    __shared__ float ss[128];
    __shared__ float red[8];

    int tid = threadIdx.x;
    int b  = tid & 63;
    int lr = tid >> 6;
    int blk = blockIdx.x;
    bool activeA = (blk < 128);
    bool isA = (blk < 64);
    int rbase = blk << 3;

    if (activeA) {
        const float* Wsrc = isA ? Wr : Wt;
        int roff = isA ? rbase : (rbase - 512);
        for (int idx = tid; idx < 8 * 128; idx += 256) {
            int row = idx >> 7;
            int c4  = (idx & 127) << 2;
            *(float4*)&ws2[row][c4] = *(const float4*)(Wsrc + (size_t)(roff + row) * kH + c4);
        }
        for (int i = tid; i < 512; i += 256) wvs[i] = w_att[i];
    }
    grid_barrier();

    const float* w0 = ws2[(lr << 1) + 0];
    const float* w1 = ws2[(lr << 1) + 1];
    int r0g = rbase + (lr << 1);

    for (int t = 0; t < kHL; t++) {
        // ---- phase A ----
        if (activeA) {
            float a0 = 0.f, a1v = 0.f;
            float4 pre[4];
#pragma unroll
            for (int i2 = 0; i2 < 4; i2++) {
                int lin = tid + (i2 << 8);
                pre[i2] = __ldcg((const float4*)(g_rT +
                    (size_t)(lin >> 4) * 64 + ((lin & 15) << 2)));
            }
            for (int cch = 0; cch < 8; cch++) {
                __syncthreads();
#pragma unroll
                for (int i2 = 0; i2 < 4; i2++) {
                    int lin = tid + (i2 << 8);
                    *(float4*)&rsT[lin >> 4][(lin & 15) << 2] = pre[i2];
                }
                __syncthreads();
                if (cch < 7) {
#pragma unroll
                    for (int i2 = 0; i2 < 4; i2++) {
                        int lin = tid + (i2 << 8);
                        pre[i2] = __ldcg((const float4*)(g_rT +
                            (size_t)((cch + 1) * 64 + (lin >> 4)) * 64 +
                            ((lin & 15) << 2)));
                    }
                }
                int kw = cch << 6;
#pragma unroll 8
                for (int kk = 0; kk < 64; kk += 4) {
                    float r0 = rsT[kk+0][b], r1 = rsT[kk+1][b];
                    float r2 = rsT[kk+2][b], r3 = rsT[kk+3][b];
                    float4 u = *(const float4*)(w0 + kw + kk);
                    float4 v = *(const float4*)(w1 + kw + kk);
                    a0  += r0*u.x + r1*u.y + r2*u.z + r3*u.w;
                    a1v += r0*v.x + r1*v.y + r2*v.z + r3*v.w;
                }
            }
            if (isA) {
                const float* qw = g_qWhT + (size_t)t * kH * 64;
                g_a2T[(size_t)(r0g    ) * 64 + b] = a0  + qw[(size_t)(r0g    ) * 64 + b];
                g_a2T[(size_t)(r0g + 1) * 64 + b] = a1v + qw[(size_t)(r0g + 1) * 64 + b];
            } else {
                g_rtT[(size_t)(r0g - 512) * 64 + b] = ftanh(a0);
                g_rtT[(size_t)(r0g - 511) * 64 + b] = ftanh(a1v);
            }
        }
        grid_barrier();

        // ---- phase B1: scores; 128 blocks, (bb, p-half) each ----
        if (activeA) {
            int bb = blk >> 1;
            int ph = blk & 1;
            for (int i = tid; i < 512; i += 256)
                a2s[i] = __ldcg(g_a2T + (size_t)i * 64 + bb);
            __syncthreads();

            int wid = tid >> 5, lane = tid & 31;
            int pbase = ph << 6;
            for (int p = pbase + wid; p < pbase + 64; p += 8) {
                const float* a1p = g_a1 + ((size_t)bb * kPL + p) * kH;
                float part = 0.f;
#pragma unroll
                for (int c2 = 0; c2 < 4; c2++) {
                    int kk = c2 * 128 + (lane << 2);
                    float4 av  = *(const float4*)(a1p + kk);
                    float4 a2v = *(const float4*)&a2s[kk];
                    float4 wv4 = *(const float4*)&wvs[kk];
                    part += wv4.x * htanh(av.x + a2v.x) + wv4.y * htanh(av.y + a2v.y)
                          + wv4.z * htanh(av.z + a2v.z) + wv4.w * htanh(av.w + a2v.w);
                }
#pragma unroll
                for (int o = 16; o; o >>= 1)
                    part += __shfl_xor_sync(0xffffffffu, part, o);
                if (lane == 0) g_ss[bb * kPL + p] = part;
            }
        }
        grid_barrier();

        // ---- phase B2: softmax + r update; blocks 0..63 ----
        if (isA) {
            int bb = blk;
            if (tid < 128) ss[tid] = __ldcg(g_ss + bb * kPL + tid);
            __syncthreads();

            float v = (tid < 128) ? ss[tid] : -3.4e38f;
#pragma unroll
            for (int o = 16; o; o >>= 1) v = fmaxf(v, __shfl_xor_sync(0xffffffffu, v, o));
            if ((tid & 31) == 0) red[tid >> 5] = v;
            __syncthreads();
            float mx = red[0];
#pragma unroll
            for (int w = 1; w < 8; w++) mx = fmaxf(mx, red[w]);
            __syncthreads();
            float e = 0.f;
            if (tid < 128) e = __expf(ss[tid] - mx);
            float sv = e;
#pragma unroll
            for (int o = 16; o; o >>= 1) sv += __shfl_xor_sync(0xffffffffu, sv, o);
            if ((tid & 31) == 0) red[tid >> 5] = sv;
            __syncthreads();
            float tot = 0.f;
#pragma unroll
            for (int w = 0; w < 8; w++) tot += red[w];
            if (tid < 128) ss[tid] = __fdividef(e, tot);
            __syncthreads();

            for (int hh = tid; hh < kH; hh += 256) {
                float acc = __ldcg(g_rtT + (size_t)hh * 64 + bb);
                const float* op = g_outp + (size_t)bb * kPL * kH + hh;
#pragma unroll 8
                for (int p2 = 0; p2 < kPL; p2++)
                    acc += op[(size_t)p2 * kH] * ss[p2];
                g_rT[(size_t)hh * 64 + bb] = acc;
                if (t == kHL - 1) g_r[bb * kH + hh] = acc;
            }
        }
        grid_barrier();
    }
}

// ---------------- final head ----------------
__global__ void __launch_bounds__(128) final_rep(
    const float* __restrict__ w1, const float* __restrict__ b1,
    const float* __restrict__ w2, const float* __restrict__ b2)
{
    __shared__ float rs[64][33];
    __shared__ float hs[64][33];
    int tid = threadIdx.x;
    int b = tid & 63;
    int j = (blockIdx.x << 1) + (tid >> 6);

    float acc1 = 0.f, acc2 = 0.f;
    const float* w1p = w1 + (size_t)j * kH;
    const float* w2p = w2 + (size_t)j * kH;

    for (int k0 = 0; k0 < kH; k0 += 32) {
#pragma unroll
        for (int i = 0; i < 4; i++) {
            int l = i * 128 + tid;
            int row = l >> 3;
            int c4 = (l & 7) << 2;
            float4 rv = *(const float4*)(g_r + row * kH + k0 + c4);
            float4 hv = *(const float4*)(g_hn + row * kH + k0 + c4);
            rs[row][c4 + 0] = rv.x; rs[row][c4 + 1] = rv.y;
            rs[row][c4 + 2] = rv.z; rs[row][c4 + 3] = rv.w;
            hs[row][c4 + 0] = hv.x; hs[row][c4 + 1] = hv.y;
            hs[row][c4 + 2] = hv.z; hs[row][c4 + 3] = hv.w;
        }
        __syncthreads();
#pragma unroll
        for (int k = 0; k < 32; k += 4) {
            float4 w1v = *(const float4*)(w1p + k0 + k);
            float4 w2v = *(const float4*)(w2p + k0 + k);
            acc1 += rs[b][k]*w1v.x + rs[b][k+1]*w1v.y + rs[b][k+2]*w1v.z + rs[b][k+3]*w1v.w;
            acc2 += hs[b][k]*w2v.x + hs[b][k+1]*w2v.y + hs[b][k+2]*w2v.z + hs[b][k+3]*w2v.w;
        }
        __syncthreads();
    }
    g_rep[b * kH + j] = ftanh(acc1 + b1[j] + acc2 + b2[j]);
}

__global__ void final_out_k(const float* __restrict__ fc3w,
                            const float* __restrict__ fc3b, float* __restrict__ out)
{
    int b = blockIdx.x, c = blockIdx.y, lane = threadIdx.x;
    float acc = 0.f;
    for (int k = lane; k < kH; k += 32)
        acc += g_rep[b * kH + k] * fc3w[c * kH + k];
#pragma unroll
    for (int o = 16; o; o >>= 1) acc += __shfl_xor_sync(0xffffffffu, acc, o);
    if (lane == 0) out[b * kC + c] = acc + fc3b[c];
}

// ---------------- launch ----------------
extern "C" void kernel_launch(void* const* d_in, const int* in_sizes, int n_in,
                              void* d_out, int out_size)
{
    const void *p_tokP, *p_tokH, *p_emb, *p_fc3w, *p_fc3b;
    const void *wih[2], *whh[2], *bia[4], *sq[6], *v512[3];
    int nwih, nwhh, nbia, nsq, nv;

    auto try_bind = [&](long long mult) -> bool {
        p_tokP = p_tokH = p_emb = p_fc3w = p_fc3b = 0;
        nwih = nwhh = nbia = nsq = nv = 0;
        for (int i = 0; i < 2; i++) { wih[i] = 0; whh[i] = 0; }
        for (int i = 0; i < 4; i++) bia[i] = 0;
        for (int i = 0; i < 6; i++) sq[i] = 0;
        for (int i = 0; i < 3; i++) v512[i] = 0;
        bool over = false;
        for (int i = 0; i < n_in; i++) {
            long long s = (long long)in_sizes[i];
            const void* p = d_in[i];
            if      (s == (long long)kB * kPL * mult)  { if (p_tokP) over = true; p_tokP = p; }
            else if (s == (long long)kB * kHL * mult)  { if (p_tokH) over = true; p_tokH = p; }
            else if (s == (long long)kV * kE * mult)   { if (p_emb)  over = true; p_emb  = p; }
            else if (s == (long long)kH4 * kE * mult)  { if (nwih < 2) wih[nwih++] = p; else over = true; }
            else if (s == (long long)kH4 * kH * mult)  { if (nwhh < 2) whh[nwhh++] = p; else over = true; }
            else if (s == (long long)kH4 * mult)       { if (nbia < 4) bia[nbia++] = p; else over = true; }
            else if (s == (long long)kH * kH * mult)   { if (nsq  < 6) sq [nsq++]  = p; else over = true; }
            else if (s == (long long)kH * mult)        { if (nv   < 3) v512[nv++]  = p; else over = true; }
            else if (s == (long long)kC * kH * mult)   { if (p_fc3w) over = true; p_fc3w = p; }
            else if (s == (long long)kC * mult)        { if (p_fc3b) over = true; p_fc3b = p; }
        }
        return !over && p_tokP && p_tokH && p_emb && p_fc3w && p_fc3b &&
               nwih == 2 && nwhh == 2 && nbia == 4 && nsq == 6 && nv == 3;
    };

    bool ok = try_bind(1);
    if (!ok) ok = try_bind(4);
    if (!ok && n_in >= 22) {
        p_tokP = d_in[0];  p_tokH = d_in[1];  p_emb = d_in[2];
        wih[0] = d_in[3];  whh[0] = d_in[4];  bia[0] = d_in[5];  bia[1] = d_in[6];
        wih[1] = d_in[7];  whh[1] = d_in[8];  bia[2] = d_in[9];  bia[3] = d_in[10];
        sq[0]  = d_in[11]; sq[1]  = d_in[12]; sq[2]  = d_in[13]; sq[3] = d_in[14];
        v512[0]= d_in[15];
        sq[4]  = d_in[16]; v512[1]= d_in[17];
        sq[5]  = d_in[18]; v512[2]= d_in[19];
        p_fc3w = d_in[20]; p_fc3b = d_in[21];
        ok = true;
    }
    if (!ok) {
        int n = out_size / 4;  if (n < 1) n = 1;
        zero_out_k<<<(n + 255) / 256, 256>>>((float*)d_out, n);
        return;
    }

    const int*   premise = (const int*)p_tokP;
    const int*   hyp     = (const int*)p_tokH;
    const float* emb     = (const float*)p_emb;
    const float* Wih1 = (const float*)wih[0]; const float* Whh1 = (const float*)whh[0];
    const float* Wih2 = (const float*)wih[1]; const float* Whh2 = (const float*)whh[1];
    const float* bih1 = (const float*)bia[0]; const float* bhh1 = (const float*)bia[1];
    const float* bih2 = (const float*)bia[2]; const float* bhh2 = (const float*)bia[3];
    const float* W_y  = (const float*)sq[0];  const float* W_h  = (const float*)sq[1];
    const float* W_r  = (const float*)sq[2];  const float* W_t  = (const float*)sq[3];
    const float* fc1_w= (const float*)sq[4];  const float* fc2_w= (const float*)sq[5];
    const float* w_att= (const float*)v512[0];
    const float* fc1_b= (const float*)v512[1];const float* fc2_b= (const float*)v512[2];
    const float* fc3_w= (const float*)p_fc3w; const float* fc3_b= (const float*)p_fc3b;
    float* out = (float*)d_out;

    zero_init<<<128, 256>>>();

    dim3 gP(kH4 / 64, (kPL * kB) / 64);
    gemm64<<<gP, 256>>>(0, emb, premise, Wih1, bih1, bhh1, kH4, kE, kPL);
    dim3 gHyp(kH4 / 64, (kHL * kB) / 64);
    gemm64<<<gHyp, 256>>>(1, emb, hyp, Wih2, bih2, bhh2, kH4, kE, kHL);

    lstm_persist<<<NBLKP, 256>>>(Whh1, Whh2);

    dim3 gA1(kH / 64, (kB * kPL) / 64);
    gemm64<<<gA1, 256>>>(2, nullptr, nullptr, W_y, nullptr, nullptr, kH, kH, 0);
    dim3 gQ(kH / 64, (kB * kHL) / 64);
    gemm64<<<gQ, 256>>>(3, nullptr, nullptr, W_h, nullptr, nullptr, kH, kH, 0);

    att_persist<<<NBLKP, 256>>>(W_r, W_t, w_att);

    final_rep<<<256, 128>>>(fc1_w, fc1_b, fc2_w, fc2_b);
    dim3 gO(kB, kC);
    final_out_k<<<gO, 32>>>(fc3_w, fc3_b, out);
}